// round 2
// baseline (speedup 1.0000x reference)
#include <cuda_runtime.h>
#include <cuda_bf16.h>

// Problem constants
#define NB 32          // batch
#define CH 128         // channels
#define HH 64
#define WW 64
#define PP 4096        // H*W
#define K3 384         // 3*C
#define SPLITS 8       // split-K for t9

// Scratch (device globals: allocation-free rule).
// NOTE: these must ONLY be referenced from device code. Passing them as
// kernel arguments from host silently binds the host shadow symbol (ATS on
// GB300 makes that dereferenceable -> silent wrong results).
__device__ float g_t3 [NB * CH * PP];           // 67 MB
__device__ float g_t5 [NB * CH * PP];           // 67 MB
__device__ float g_t6 [NB * CH * PP];           // 67 MB
__device__ float g_t9 [NB * CH * K3];           // 6.3 MB
__device__ float g_t9p[SPLITS * NB * CH * K3];  // 50 MB split-K partials
__device__ float g_t12[NB * K3 * PP];           // 201 MB

// ---------------------------------------------------------------------------
// E1: t5[n,c,p] = p5[p] * max(x[w-2], x[w], x[w+2])
// ---------------------------------------------------------------------------
__global__ void t5_kernel(const float* __restrict__ x, const float* __restrict__ p5)
{
    int i = blockIdx.x * 256 + threadIdx.x;
    if (i >= NB * CH * PP) return;
    int p = i & (PP - 1);
    int w = p & 63;
    float v1 = (w >= 2)  ? x[i - 2] : 0.f;
    float v2 = x[i];
    float v3 = (w < 62)  ? x[i + 2] : 0.f;
    g_t5[i] = p5[p] * fmaxf(v1, fmaxf(v2, v3));
}

// ---------------------------------------------------------------------------
// GEMM (weight @ gathered-B): C[n, o, p] = sum_k A[o,k] * B[n,k,p]
// MODE 0: B[k,p] = x shifted in w (t1)   -> writes g_t3 (A = w3)
// MODE 1: B[k,p] = g_t5 shifted in h     -> writes g_t6 (A = w6 as [128][384])
// 128x128 tile, 256 threads, 8x8 micro-tile, k-slab 16
// ---------------------------------------------------------------------------
template <int MODE>
__global__ void __launch_bounds__(256)
gemm_aw_kernel(const float* __restrict__ A, const float* __restrict__ x)
{
    const int n  = blockIdx.y;
    const int pt = blockIdx.x * 128;

    __shared__ float As[16][128];   // [kk][o]
    __shared__ float Bs[16][128];   // [kk][p]

    const int tid = threadIdx.x;
    const int tx = tid & 15;        // -> p micro
    const int ty = tid >> 4;        // -> o micro

    const int a_o  = tid >> 1;
    const int a_k0 = (tid & 1) * 8;
    const int b_k  = tid >> 4;
    const int b_p0 = (tid & 15) * 8;

    const float* bbase = (MODE == 0 ? x : (const float*)g_t5) + (size_t)n * CH * PP;

    float acc[8][8];
#pragma unroll
    for (int i = 0; i < 8; i++)
#pragma unroll
        for (int j = 0; j < 8; j++) acc[i][j] = 0.f;

    for (int kt = 0; kt < K3; kt += 16) {
        // load A slab (transposed into [kk][o])
#pragma unroll
        for (int u = 0; u < 8; u++)
            As[a_k0 + u][a_o] = A[a_o * K3 + kt + a_k0 + u];
        // load B slab (gathered)
        {
            int k  = kt + b_k;
            int cp = k / 3;
            int m  = k - cp * 3;
#pragma unroll
            for (int u = 0; u < 8; u++) {
                int p = pt + b_p0 + u;
                float v;
                if (MODE == 0) {
                    int w  = p & 63;
                    int wp = w + 2 * m - 2;
                    v = (wp >= 0 && wp < 64) ? bbase[cp * PP + (p - w) + wp] : 0.f;
                } else {
                    int h  = p >> 6;
                    int hp = h + 3 * m - 3;
                    v = (hp >= 0 && hp < 64) ? bbase[cp * PP + hp * 64 + (p & 63)] : 0.f;
                }
                Bs[b_k][b_p0 + u] = v;
            }
        }
        __syncthreads();
#pragma unroll
        for (int kk = 0; kk < 16; kk++) {
            float a[8], b[8];
#pragma unroll
            for (int i = 0; i < 8; i++) a[i] = As[kk][ty * 8 + i];
#pragma unroll
            for (int j = 0; j < 8; j++) b[j] = Bs[kk][tx * 8 + j];
#pragma unroll
            for (int i = 0; i < 8; i++)
#pragma unroll
                for (int j = 0; j < 8; j++) acc[i][j] = fmaf(a[i], b[j], acc[i][j]);
        }
        __syncthreads();
    }

    float* cb = (MODE == 0 ? (float*)g_t3 : (float*)g_t6) + (size_t)n * CH * PP + pt;
#pragma unroll
    for (int i = 0; i < 8; i++) {
        int o = ty * 8 + i;
#pragma unroll
        for (int j = 0; j < 8; j++)
            cb[o * PP + tx * 8 + j] = acc[i][j];
    }
}

// ---------------------------------------------------------------------------
// GEMM t9 (split-K, deterministic partials):
// t9p[s,n,c,k] = sum_{p in segment s} (p8[c]*max(x,t6))[n,c,p] * t1[n,k,p]
// ---------------------------------------------------------------------------
__global__ void __launch_bounds__(256)
gemm_t9_kernel(const float* __restrict__ x, const float* __restrict__ p8)
{
    const int kt = blockIdx.x * 128;   // 0..2 tiles of k
    const int n  = blockIdx.y;
    const int s  = blockIdx.z;
    const int pbase = s * (PP / SPLITS);  // 512 per split

    __shared__ float As[16][128];   // [pp][c]
    __shared__ float Bs[16][128];   // [pp][k]

    const int tid = threadIdx.x;
    const int tx = tid & 15;        // -> k micro
    const int ty = tid >> 4;        // -> c micro

    const int l_r  = tid >> 1;
    const int l_p0 = (tid & 1) * 8;

    const float* xb  = x    + (size_t)n * CH * PP;
    const float* t6b = g_t6 + (size_t)n * CH * PP;

    float acc[8][8];
#pragma unroll
    for (int i = 0; i < 8; i++)
#pragma unroll
        for (int j = 0; j < 8; j++) acc[i][j] = 0.f;

    const float p8c = p8[l_r];
    const int k  = kt + l_r;
    const int cp = k / 3;
    const int m  = k - cp * 3;

    for (int pt = pbase; pt < pbase + PP / SPLITS; pt += 16) {
#pragma unroll
        for (int u = 0; u < 8; u++) {
            int idx = l_r * PP + pt + l_p0 + u;
            As[l_p0 + u][l_r] = p8c * fmaxf(xb[idx], t6b[idx]);
        }
#pragma unroll
        for (int u = 0; u < 8; u++) {
            int p  = pt + l_p0 + u;
            int w  = p & 63;
            int wp = w + 2 * m - 2;
            Bs[l_p0 + u][l_r] = (wp >= 0 && wp < 64) ? xb[cp * PP + (p - w) + wp] : 0.f;
        }
        __syncthreads();
#pragma unroll
        for (int pp = 0; pp < 16; pp++) {
            float a[8], b[8];
#pragma unroll
            for (int i = 0; i < 8; i++) a[i] = As[pp][ty * 8 + i];
#pragma unroll
            for (int j = 0; j < 8; j++) b[j] = Bs[pp][tx * 8 + j];
#pragma unroll
            for (int i = 0; i < 8; i++)
#pragma unroll
                for (int j = 0; j < 8; j++) acc[i][j] = fmaf(a[i], b[j], acc[i][j]);
        }
        __syncthreads();
    }

    float* ob = g_t9p + ((size_t)s * NB + n) * CH * K3 + kt;
#pragma unroll
    for (int i = 0; i < 8; i++)
#pragma unroll
        for (int j = 0; j < 8; j++)
            ob[(ty * 8 + i) * K3 + tx * 8 + j] = acc[i][j];
}

__global__ void reduce_t9_kernel()
{
    int i = blockIdx.x * 256 + threadIdx.x;
    if (i >= NB * CH * K3) return;
    float sum = 0.f;
#pragma unroll
    for (int u = 0; u < SPLITS; u++)
        sum += g_t9p[(size_t)u * NB * CH * K3 + i];
    g_t9[i] = sum * (1.0f / 64.0f);   // / sqrt(HW)
}

// ---------------------------------------------------------------------------
// E2: t12[n,k,p] = p12[j,h] * max(t6, max(x,t6) + max(t3, t1))
// ---------------------------------------------------------------------------
__global__ void t12_kernel(const float* __restrict__ x, const float* __restrict__ p12)
{
    int i = blockIdx.x * 256 + threadIdx.x;
    if (i >= NB * K3 * PP) return;
    int p = i & (PP - 1);
    int k = (i >> 12) % K3;
    int n = i / (K3 * PP);
    int cp = k / 3;
    int j  = k - cp * 3;
    int h  = p >> 6;
    int w  = p & 63;
    size_t base = ((size_t)n * CH + cp) * PP + p;
    float xv  = x[base];
    float t6v = g_t6[base];
    float t3v = g_t3[base];
    int wp = w + 2 * j - 2;
    float x1 = (wp >= 0 && wp < 64) ? x[base - w + wp] : 0.f;
    float t7 = fmaxf(xv, t6v);
    float t4 = fmaxf(t3v, x1);
    g_t12[i] = p12[j * 64 + h] * fmaxf(t6v, t7 + t4);
}

// ---------------------------------------------------------------------------
// GEMM out: out[n,c,p] = (1/sqrt(384)) * sum_k t12[n,k,p] * t9[n,c,k]
// ---------------------------------------------------------------------------
__global__ void __launch_bounds__(256)
gemm_out_kernel(float* __restrict__ out)
{
    const int pt = blockIdx.x * 128;
    const int n  = blockIdx.y;

    __shared__ float As[16][128];   // [kk][p]
    __shared__ float Bs[16][128];   // [kk][c]

    const int tid = threadIdx.x;
    const int tx = tid & 15;        // -> c micro
    const int ty = tid >> 4;        // -> p micro

    const int a_k  = tid >> 4;
    const int a_p0 = (tid & 15) * 8;
    const int b_c  = tid >> 1;
    const int b_k0 = (tid & 1) * 8;

    const float* t12b = g_t12 + (size_t)n * K3 * PP;
    const float* t9b  = g_t9  + (size_t)n * CH * K3;

    float acc[8][8];
#pragma unroll
    for (int i = 0; i < 8; i++)
#pragma unroll
        for (int j = 0; j < 8; j++) acc[i][j] = 0.f;

    for (int kt = 0; kt < K3; kt += 16) {
#pragma unroll
        for (int u = 0; u < 8; u++)
            As[a_k][a_p0 + u] = t12b[(size_t)(kt + a_k) * PP + pt + a_p0 + u];
#pragma unroll
        for (int u = 0; u < 8; u++)
            Bs[b_k0 + u][b_c] = t9b[b_c * K3 + kt + b_k0 + u];
        __syncthreads();
#pragma unroll
        for (int kk = 0; kk < 16; kk++) {
            float a[8], b[8];
#pragma unroll
            for (int i = 0; i < 8; i++) a[i] = As[kk][ty * 8 + i];
#pragma unroll
            for (int j = 0; j < 8; j++) b[j] = Bs[kk][tx * 8 + j];
#pragma unroll
            for (int i = 0; i < 8; i++)
#pragma unroll
                for (int j = 0; j < 8; j++) acc[i][j] = fmaf(a[i], b[j], acc[i][j]);
        }
        __syncthreads();
    }

    const float scale = 0.051031036307982884f;  // 1/sqrt(384)
    float* ob = out + (size_t)n * CH * PP + pt;
#pragma unroll
    for (int j = 0; j < 8; j++) {
        int c = tx * 8 + j;
#pragma unroll
        for (int i = 0; i < 8; i++)
            ob[(size_t)c * PP + ty * 8 + i] = acc[i][j] * scale;
    }
}

// ---------------------------------------------------------------------------
extern "C" void kernel_launch(void* const* d_in, const int* in_sizes, int n_in,
                              void* d_out, int out_size)
{
    const float* x   = (const float*)d_in[0];  // [N,C,H,W]
    const float* w3  = (const float*)d_in[1];  // [C,3C]
    const float* p5  = (const float*)d_in[2];  // [H,W]
    const float* w6  = (const float*)d_in[3];  // [C,C,3,1] == [C,3C] with k=i*3+kh
    const float* p8  = (const float*)d_in[4];  // [C]
    const float* p12 = (const float*)d_in[5];  // [3,H]
    float* out = (float*)d_out;

    // 1) t5 = p5 * max3(x shifts)
    t5_kernel<<<(NB * CH * PP) / 256, 256>>>(x, p5);
    // 2) t3 = w3 @ t1
    gemm_aw_kernel<0><<<dim3(PP / 128, NB), 256>>>(w3, x);
    // 3) t6 = w6 (*) t5  (h-dilated conv as GEMM)
    gemm_aw_kernel<1><<<dim3(PP / 128, NB), 256>>>(w6, x);
    // 4) t9 partials (split-K) + deterministic reduce
    gemm_t9_kernel<<<dim3(K3 / 128, NB, SPLITS), 256>>>(x, p8);
    reduce_t9_kernel<<<(NB * CH * K3) / 256, 256>>>();
    // 5) t12 elementwise
    t12_kernel<<<(NB * K3 * PP) / 256, 256>>>(x, p12);
    // 6) out = (t12^T @ t9^T) / sqrt(384)
    gemm_out_kernel<<<dim3(PP / 128, NB), 256>>>(out);
}

// round 3
// speedup vs baseline: 1.7390x; 1.7390x over previous
#include <cuda_runtime.h>
#include <cuda_bf16.h>

// Problem constants
#define NB 32
#define CH 128
#define PP 4096        // H*W (64*64)
#define K3 384         // 3*C
#define SPLITS 8       // split-K for t9
#define SST 34         // smem row stride in bf16 elems (17 words -> conflict-free)

// Scratch (device globals; must only be referenced from device code)
__device__ float g_t3 [NB * CH * PP];
__device__ float g_t5 [NB * CH * PP];
__device__ float g_t6 [NB * CH * PP];
__device__ float g_t9 [NB * CH * K3];
__device__ float g_t9p[SPLITS * NB * CH * K3];
__device__ float g_t12[(size_t)NB * K3 * PP];

// ---------------------------------------------------------------------------
__global__ void t5_kernel(const float* __restrict__ x, const float* __restrict__ p5)
{
    int i = blockIdx.x * 256 + threadIdx.x;
    if (i >= NB * CH * PP) return;
    int p = i & (PP - 1);
    int w = p & 63;
    float v1 = (w >= 2) ? x[i - 2] : 0.f;
    float v2 = x[i];
    float v3 = (w < 62) ? x[i + 2] : 0.f;
    g_t5[i] = p5[p] * fmaxf(v1, fmaxf(v2, v3));
}

// ---------------------------------------------------------------------------
// t12[n,k,p] = p12[j,h] * max(t6, max(x,t6) + max(t3, t1))
// ---------------------------------------------------------------------------
__global__ void t12_kernel(const float* __restrict__ x, const float* __restrict__ p12)
{
    size_t i = (size_t)blockIdx.x * 256 + threadIdx.x;
    if (i >= (size_t)NB * K3 * PP) return;
    int p = (int)(i & (PP - 1));
    int k = (int)((i >> 12) % K3);
    int n = (int)(i / ((size_t)K3 * PP));
    int cp = k / 3;
    int j  = k - cp * 3;
    int h  = p >> 6;
    int w  = p & 63;
    size_t base = ((size_t)n * CH + cp) * PP + p;
    float xv  = x[base];
    float t6v = g_t6[base];
    float t3v = g_t3[base];
    int wp = w + 2 * j - 2;
    float x1 = (wp >= 0 && wp < 64) ? x[base - w + wp] : 0.f;
    g_t12[i] = p12[j * 64 + h] * fmaxf(t6v, fmaxf(xv, t6v) + fmaxf(t3v, x1));
}

__global__ void reduce_t9_kernel()
{
    int i = blockIdx.x * 256 + threadIdx.x;
    if (i >= NB * CH * K3) return;
    float sum = 0.f;
#pragma unroll
    for (int u = 0; u < SPLITS; u++)
        sum += g_t9p[(size_t)u * NB * CH * K3 + i];
    g_t9[i] = sum * (1.0f / 64.0f);
}

// ---------------------------------------------------------------------------
// HMMA helper
// ---------------------------------------------------------------------------
__device__ __forceinline__ void mma_bf16(float& d0, float& d1, float& d2, float& d3,
                                         unsigned a0, unsigned a1, unsigned a2, unsigned a3,
                                         unsigned b0, unsigned b1)
{
    asm volatile(
        "mma.sync.aligned.m16n8k16.row.col.f32.bf16.bf16.f32 "
        "{%0,%1,%2,%3},{%4,%5,%6,%7},{%8,%9},{%0,%1,%2,%3};\n"
        : "+f"(d0), "+f"(d1), "+f"(d2), "+f"(d3)
        : "r"(a0), "r"(a1), "r"(a2), "r"(a3), "r"(b0), "r"(b1));
}

// pack 2 fp32 -> (hi bf162, lo bf162)
__device__ __forceinline__ void split2(float v0, float v1, unsigned& hi, unsigned& lo)
{
    __nv_bfloat16 h0 = __float2bfloat16(v0);
    __nv_bfloat16 h1 = __float2bfloat16(v1);
    __nv_bfloat16 l0 = __float2bfloat16(v0 - __bfloat162float(h0));
    __nv_bfloat16 l1 = __float2bfloat16(v1 - __bfloat162float(h1));
    __nv_bfloat162 hh = __halves2bfloat162(h0, h1);
    __nv_bfloat162 ll = __halves2bfloat162(l0, l1);
    hi = *reinterpret_cast<unsigned*>(&hh);
    lo = *reinterpret_cast<unsigned*>(&ll);
}

// ---------------------------------------------------------------------------
// Unified tensor-core GEMM:  C[m, n] = sum_k A[m,k] * B[n,k]
//   MODE 0: t3  = w3 @ t1        m=o(128), n=p tile, k=384
//   MODE 1: t6  = w6 (*) t5      m=o(128), n=p tile, k=384
//   MODE 2: t9  partials         m=c(128), n=j tile, k=p (512/split)
//   MODE 3: out = t9 @ t12       m=c(128), n=p tile, k=384
// block: 128x128 tile, 256 thr (8 warps as 2m x 4n of 64x32), k-slab 32.
// bf16 hi/lo split, 3 MMAs, fp32 accumulate.
// ---------------------------------------------------------------------------
template <int MODE>
__global__ void __launch_bounds__(256)
mma_gemm_kernel(const float* __restrict__ x, const float* __restrict__ Aw,
                const float* __restrict__ p8, float* __restrict__ Cdst)
{
    const int KTOT = (MODE == 2) ? 512 : 384;
    const int nb = blockIdx.y;
    const int nt0 = blockIdx.x * 128;                 // n-tile base (p or j)
    const int kbase = (MODE == 2) ? blockIdx.z * 512 : 0;

    __shared__ __nv_bfloat16 Ah[128 * SST], Al[128 * SST];
    __shared__ __nv_bfloat16 Bh[128 * SST], Bl[128 * SST];

    const int tid = threadIdx.x;
    const int wid = tid >> 5;
    const int lane = tid & 31;
    const int g = lane >> 2, c = lane & 3;
    const int wm = (wid >> 2) * 64;                   // warp m base
    const int wn = (wid & 3) * 32;                    // warp n base

    // loader A: m = tid>>1, 16 consecutive k at (tid&1)*16
    const int la_m = tid >> 1;
    const int la_k0 = (tid & 1) * 16;
    // loader B: n = tid&127, 16 consecutive k at (tid>>7)*16
    const int lb_n = tid & 127;
    const int lb_k0 = (tid >> 7) * 16;

    const float* xb = x + (size_t)nb * CH * PP;

    float acc[4][4][4];
#pragma unroll
    for (int i = 0; i < 4; i++)
#pragma unroll
        for (int j = 0; j < 4; j++)
#pragma unroll
            for (int r = 0; r < 4; r++) acc[i][j][r] = 0.f;

    // MODE2 B: loop-invariant channel decomposition of j
    int b_cp = 0, b_mm = 0;
    if (MODE == 2) { int j = nt0 + lb_n; b_cp = j / 3; b_mm = j - b_cp * 3; }

    for (int kt = 0; kt < KTOT; kt += 32) {
        // ---- load A slab ----
        {
            float v[16];
#pragma unroll
            for (int u = 0; u < 16; u++) {
                int k = kt + la_k0 + u;
                if (MODE == 0 || MODE == 1) v[u] = Aw[la_m * K3 + k];
                else if (MODE == 2) {
                    int p = kbase + k;
                    size_t idx = (size_t)la_m * PP + p;
                    v[u] = p8[la_m] * fmaxf(xb[idx], g_t6[(size_t)nb * CH * PP + idx]);
                } else {
                    v[u] = g_t9[(size_t)nb * CH * K3 + la_m * K3 + k];
                }
            }
#pragma unroll
            for (int u = 0; u < 8; u++) {
                unsigned hi, lo;
                split2(v[2 * u], v[2 * u + 1], hi, lo);
                *reinterpret_cast<unsigned*>(&Ah[la_m * SST + la_k0 + 2 * u]) = hi;
                *reinterpret_cast<unsigned*>(&Al[la_m * SST + la_k0 + 2 * u]) = lo;
            }
        }
        // ---- load B slab ----
        {
            float v[16];
#pragma unroll
            for (int u = 0; u < 16; u++) {
                int k = kt + lb_k0 + u;
                if (MODE == 0) {
                    int p = nt0 + lb_n;
                    int cp = k / 3, mm = k - cp * 3;
                    int w = p & 63, wp = w + 2 * mm - 2;
                    v[u] = (wp >= 0 && wp < 64) ? xb[cp * PP + (p - w) + wp] : 0.f;
                } else if (MODE == 1) {
                    int p = nt0 + lb_n;
                    int cp = k / 3, mm = k - cp * 3;
                    int h = p >> 6, hp = h + 3 * mm - 3;
                    v[u] = (hp >= 0 && hp < 64)
                         ? g_t5[(size_t)nb * CH * PP + cp * PP + hp * 64 + (p & 63)] : 0.f;
                } else if (MODE == 2) {
                    int p = kbase + k;
                    int w = p & 63, wp = w + 2 * b_mm - 2;
                    v[u] = (wp >= 0 && wp < 64) ? xb[b_cp * PP + (p - w) + wp] : 0.f;
                } else {
                    int p = nt0 + lb_n;
                    v[u] = g_t12[(size_t)nb * K3 * PP + (size_t)k * PP + p];
                }
            }
#pragma unroll
            for (int u = 0; u < 8; u++) {
                unsigned hi, lo;
                split2(v[2 * u], v[2 * u + 1], hi, lo);
                *reinterpret_cast<unsigned*>(&Bh[lb_n * SST + lb_k0 + 2 * u]) = hi;
                *reinterpret_cast<unsigned*>(&Bl[lb_n * SST + lb_k0 + 2 * u]) = lo;
            }
        }
        __syncthreads();

        // ---- compute: 2 k16 steps ----
#pragma unroll
        for (int ks = 0; ks < 2; ks++) {
            const int kk = ks * 16 + 2 * c;
            unsigned bh[4][2], bl[4][2];
#pragma unroll
            for (int nt = 0; nt < 4; nt++) {
                int nr = (wn + nt * 8 + g) * SST + kk;
                bh[nt][0] = *reinterpret_cast<unsigned*>(&Bh[nr]);
                bh[nt][1] = *reinterpret_cast<unsigned*>(&Bh[nr + 8]);
                bl[nt][0] = *reinterpret_cast<unsigned*>(&Bl[nr]);
                bl[nt][1] = *reinterpret_cast<unsigned*>(&Bl[nr + 8]);
            }
#pragma unroll
            for (int mt = 0; mt < 4; mt++) {
                int mr0 = (wm + mt * 16 + g) * SST + kk;
                int mr1 = mr0 + 8 * SST;
                unsigned ah0 = *reinterpret_cast<unsigned*>(&Ah[mr0]);
                unsigned ah1 = *reinterpret_cast<unsigned*>(&Ah[mr1]);
                unsigned ah2 = *reinterpret_cast<unsigned*>(&Ah[mr0 + 8]);
                unsigned ah3 = *reinterpret_cast<unsigned*>(&Ah[mr1 + 8]);
                unsigned al0 = *reinterpret_cast<unsigned*>(&Al[mr0]);
                unsigned al1 = *reinterpret_cast<unsigned*>(&Al[mr1]);
                unsigned al2 = *reinterpret_cast<unsigned*>(&Al[mr0 + 8]);
                unsigned al3 = *reinterpret_cast<unsigned*>(&Al[mr1 + 8]);
#pragma unroll
                for (int nt = 0; nt < 4; nt++) {
                    float* a = acc[mt][nt];
                    mma_bf16(a[0], a[1], a[2], a[3], ah0, ah1, ah2, ah3, bh[nt][0], bh[nt][1]);
                    mma_bf16(a[0], a[1], a[2], a[3], ah0, ah1, ah2, ah3, bl[nt][0], bl[nt][1]);
                    mma_bf16(a[0], a[1], a[2], a[3], al0, al1, al2, al3, bh[nt][0], bh[nt][1]);
                }
            }
        }
        __syncthreads();
    }

    // ---- epilogue ----
    const float scale = (MODE == 3) ? 0.051031036307982884f : 1.0f;  // 1/sqrt(384)
#pragma unroll
    for (int mt = 0; mt < 4; mt++) {
#pragma unroll
        for (int nt = 0; nt < 4; nt++) {
            int m0 = wm + mt * 16 + g;
            int m1 = m0 + 8;
            int col = wn + nt * 8 + 2 * c;
            float2 v0 = make_float2(acc[mt][nt][0] * scale, acc[mt][nt][1] * scale);
            float2 v1 = make_float2(acc[mt][nt][2] * scale, acc[mt][nt][3] * scale);
            if (MODE == 0 || MODE == 1) {
                float* cb = Cdst + (size_t)nb * CH * PP + nt0;
                *reinterpret_cast<float2*>(&cb[(size_t)m0 * PP + col]) = v0;
                *reinterpret_cast<float2*>(&cb[(size_t)m1 * PP + col]) = v1;
            } else if (MODE == 2) {
                float* cb = g_t9p + ((size_t)blockIdx.z * NB + nb) * CH * K3 + nt0;
                *reinterpret_cast<float2*>(&cb[(size_t)m0 * K3 + col]) = v0;
                *reinterpret_cast<float2*>(&cb[(size_t)m1 * K3 + col]) = v1;
            } else {
                float* cb = Cdst + (size_t)nb * CH * PP + nt0;
                *reinterpret_cast<float2*>(&cb[(size_t)m0 * PP + col]) = v0;
                *reinterpret_cast<float2*>(&cb[(size_t)m1 * PP + col]) = v1;
            }
        }
    }
}

// device-symbol address bridges (host cannot take &g_* directly)
__global__ void noop() {}

extern "C" void kernel_launch(void* const* d_in, const int* in_sizes, int n_in,
                              void* d_out, int out_size)
{
    const float* x   = (const float*)d_in[0];  // [N,C,H,W]
    const float* w3  = (const float*)d_in[1];  // [C,3C]
    const float* p5  = (const float*)d_in[2];  // [H,W]
    const float* w6  = (const float*)d_in[3];  // [C,C,3,1] -> [C,3C]
    const float* p8  = (const float*)d_in[4];  // [C]
    const float* p12 = (const float*)d_in[5];  // [3,H]
    float* out = (float*)d_out;

    // resolve device symbol addresses (graph-capture safe, no alloc)
    static float* t3p = nullptr; static float* t6p = nullptr;
    if (!t3p) { cudaGetSymbolAddress((void**)&t3p, g_t3); cudaGetSymbolAddress((void**)&t6p, g_t6); }

    t5_kernel<<<(NB * CH * PP) / 256, 256>>>(x, p5);
    mma_gemm_kernel<0><<<dim3(32, NB), 256>>>(x, w3, p8, t3p);
    mma_gemm_kernel<1><<<dim3(32, NB), 256>>>(x, w6, p8, t6p);
    mma_gemm_kernel<2><<<dim3(3, NB, SPLITS), 256>>>(x, w3, p8, nullptr);
    reduce_t9_kernel<<<(NB * CH * K3) / 256, 256>>>();
    t12_kernel<<<(size_t)NB * K3 * PP / 256, 256>>>(x, p12);
    mma_gemm_kernel<3><<<dim3(32, NB), 256>>>(x, w3, p8, out);
}

// round 4
// speedup vs baseline: 1.8775x; 1.0797x over previous
#include <cuda_runtime.h>
#include <cuda_bf16.h>

#define NB 32
#define CH 128
#define PP 4096        // H*W
#define K3 384         // 3*C
#define SPLITS 4       // split-K for t9 (over p)
#define SST 34         // smem row stride (bf16 elems), 17 words
#define SMEM_BYTES (2 * 4 * 128 * SST * 2)   // 2 bufs x (Ah,Al,Bh,Bl) x 128 x SST bf16

// Scratch (device globals; only referenced from device code / via cudaGetSymbolAddress)
__device__ float g_t3 [NB * CH * PP];
__device__ float g_t5 [NB * CH * PP];
__device__ float g_t6 [NB * CH * PP];
__device__ float g_t9 [NB * CH * K3];
__device__ float g_t9p[SPLITS * NB * CH * K3];

// ---------------------------------------------------------------------------
__global__ void t5_kernel(const float* __restrict__ x, const float* __restrict__ p5)
{
    int i = blockIdx.x * 256 + threadIdx.x;
    if (i >= NB * CH * PP) return;
    int p = i & (PP - 1);
    int w = p & 63;
    float v1 = (w >= 2) ? x[i - 2] : 0.f;
    float v2 = x[i];
    float v3 = (w < 62) ? x[i + 2] : 0.f;
    g_t5[i] = p5[p] * fmaxf(v1, fmaxf(v2, v3));
}

__global__ void reduce_t9_kernel()
{
    int i = blockIdx.x * 256 + threadIdx.x;
    if (i >= NB * CH * K3) return;
    float sum = 0.f;
#pragma unroll
    for (int u = 0; u < SPLITS; u++)
        sum += g_t9p[(size_t)u * NB * CH * K3 + i];
    g_t9[i] = sum * (1.0f / 64.0f);   // / sqrt(HW)
}

// ---------------------------------------------------------------------------
__device__ __forceinline__ void mma_bf16(float& d0, float& d1, float& d2, float& d3,
                                         unsigned a0, unsigned a1, unsigned a2, unsigned a3,
                                         unsigned b0, unsigned b1)
{
    asm volatile(
        "mma.sync.aligned.m16n8k16.row.col.f32.bf16.bf16.f32 "
        "{%0,%1,%2,%3},{%4,%5,%6,%7},{%8,%9},{%0,%1,%2,%3};\n"
        : "+f"(d0), "+f"(d1), "+f"(d2), "+f"(d3)
        : "r"(a0), "r"(a1), "r"(a2), "r"(a3), "r"(b0), "r"(b1));
}

__device__ __forceinline__ void split2(float v0, float v1, unsigned& hi, unsigned& lo)
{
    __nv_bfloat16 h0 = __float2bfloat16(v0);
    __nv_bfloat16 h1 = __float2bfloat16(v1);
    __nv_bfloat16 l0 = __float2bfloat16(v0 - __bfloat162float(h0));
    __nv_bfloat16 l1 = __float2bfloat16(v1 - __bfloat162float(h1));
    __nv_bfloat162 hh = __halves2bfloat162(h0, h1);
    __nv_bfloat162 ll = __halves2bfloat162(l0, l1);
    hi = *reinterpret_cast<unsigned*>(&hh);
    lo = *reinterpret_cast<unsigned*>(&ll);
}

// ---------------------------------------------------------------------------
// Unified tensor-core GEMM:  C[m, n] = sum_k A[m,k] * B[n,k]
//   MODE 0: t3  = w3 @ t1            m=o, n=p, k=384
//   MODE 1: t6  = w6 (*) t5          m=o, n=p, k=384
//   MODE 2: t9  partials             m=c, n=j, k=p-slab (1024)
//   MODE 3: out = t9 @ t12(fused)    m=c, n=p, k=384
// 128x128 CTA tile, 8 warps (2m x 4n of 64x32), k-slab 32,
// bf16 hi/lo split (3 HMMA), double-buffered smem, register prefetch.
// ---------------------------------------------------------------------------
template <int MODE>
__global__ void __launch_bounds__(256)
mma_gemm_kernel(const float* __restrict__ x, const float* __restrict__ Aw,
                const float* __restrict__ p8, const float* __restrict__ p12,
                float* __restrict__ Cdst)
{
    extern __shared__ __nv_bfloat16 smbuf[];
    const int KTOT  = (MODE == 2) ? (PP / SPLITS) : K3;
    const int nb    = blockIdx.y;
    const int nt0   = blockIdx.x * 128;
    const int kbase = (MODE == 2) ? blockIdx.z * (PP / SPLITS) : 0;

    const int tid = threadIdx.x;
    const int wid = tid >> 5, lane = tid & 31;
    const int gq = lane >> 2, cq = lane & 3;
    const int wm = (wid >> 2) * 64, wn = (wid & 3) * 32;

    const float* xb  = x    + (size_t)nb * CH * PP;
    const float* t6b = g_t6 + (size_t)nb * CH * PP;
    const float* t3b = g_t3 + (size_t)nb * CH * PP;
    const float* t5b = g_t5 + (size_t)nb * CH * PP;

    // loader indices
    const int la_m = tid >> 1, la_k0 = (tid & 1) * 16;   // modes 0/1/3 A
    const int lb_n = tid & 127, lb_k0 = (tid >> 7) * 16; // modes 0/1/3 B
    const int l2_r = tid >> 4, l2_p0 = (tid & 15) * 2;   // mode 2 (coalesced)

    const int pB = nt0 + lb_n;
    const int wB = pB & 63;
    const int hB = pB >> 6;

    unsigned sAh[8], sAl[8], sBh[8], sBl[8];

    float acc[4][4][4];
#pragma unroll
    for (int i = 0; i < 4; i++)
#pragma unroll
        for (int j = 0; j < 4; j++)
#pragma unroll
            for (int r = 0; r < 4; r++) acc[i][j][r] = 0.f;

    auto loadA = [&](int kt) {
        if (MODE == 0 || MODE == 1) {
#pragma unroll
            for (int u = 0; u < 8; u++) {
                float v0 = Aw[la_m * K3 + kt + la_k0 + 2 * u];
                float v1 = Aw[la_m * K3 + kt + la_k0 + 2 * u + 1];
                split2(v0, v1, sAh[u], sAl[u]);
            }
        } else if (MODE == 3) {
            const float* t9b = g_t9 + (size_t)nb * CH * K3;
#pragma unroll
            for (int u = 0; u < 8; u++) {
                float v0 = t9b[la_m * K3 + kt + la_k0 + 2 * u];
                float v1 = t9b[la_m * K3 + kt + la_k0 + 2 * u + 1];
                split2(v0, v1, sAh[u], sAl[u]);
            }
        } else { // MODE 2: rows = channels, k = p (coalesced float2 per lane)
#pragma unroll
            for (int it = 0; it < 8; it++) {
                int cc = l2_r + 16 * it;
                size_t idx = (size_t)cc * PP + kbase + kt + l2_p0;
                float2 xv = *reinterpret_cast<const float2*>(&xb[idx]);
                float2 tv = *reinterpret_cast<const float2*>(&t6b[idx]);
                float s = p8[cc];
                split2(s * fmaxf(xv.x, tv.x), s * fmaxf(xv.y, tv.y), sAh[it], sAl[it]);
            }
        }
    };

    auto loadB = [&](int kt) {
        if (MODE == 0) {
#pragma unroll
            for (int u = 0; u < 8; u++) {
                float v[2];
#pragma unroll
                for (int e = 0; e < 2; e++) {
                    int k = kt + lb_k0 + 2 * u + e;
                    int cp = k / 3, m = k - 3 * cp;
                    int wq = wB + 2 * m - 2;
                    v[e] = (wq >= 0 && wq < 64) ? xb[cp * PP + (pB - wB) + wq] : 0.f;
                }
                split2(v[0], v[1], sBh[u], sBl[u]);
            }
        } else if (MODE == 1) {
#pragma unroll
            for (int u = 0; u < 8; u++) {
                float v[2];
#pragma unroll
                for (int e = 0; e < 2; e++) {
                    int k = kt + lb_k0 + 2 * u + e;
                    int cp = k / 3, m = k - 3 * cp;
                    int hp = hB + 3 * m - 3;
                    v[e] = (hp >= 0 && hp < 64) ? t5b[cp * PP + hp * 64 + wB] : 0.f;
                }
                split2(v[0], v[1], sBh[u], sBl[u]);
            }
        } else if (MODE == 3) {   // fused t12 compute
#pragma unroll
            for (int u = 0; u < 8; u++) {
                float v[2];
#pragma unroll
                for (int e = 0; e < 2; e++) {
                    int k = kt + lb_k0 + 2 * u + e;
                    int cp = k / 3, j = k - 3 * cp;
                    size_t base = (size_t)cp * PP + pB;
                    float xv  = xb[base];
                    float t6v = t6b[base];
                    float t3v = t3b[base];
                    int wq = wB + 2 * j - 2;
                    float x1 = (wq >= 0 && wq < 64) ? xb[base - wB + wq] : 0.f;
                    v[e] = p12[j * 64 + hB] *
                           fmaxf(t6v, fmaxf(xv, t6v) + fmaxf(t3v, x1));
                }
                split2(v[0], v[1], sBh[u], sBl[u]);
            }
        } else { // MODE 2: rows = j, k = p (coalesced float2 per lane)
#pragma unroll
            for (int it = 0; it < 8; it++) {
                int row = l2_r + 16 * it;
                int j = nt0 + row;
                int cp = j / 3, m = j - 3 * cp;
                int p = kbase + kt + l2_p0;
                int w = p & 63;
                int wq = w + 2 * m - 2;
                float2 bv = make_float2(0.f, 0.f);
                if (wq >= 0 && wq < 63)
                    bv = *reinterpret_cast<const float2*>(&xb[cp * PP + (p - w) + wq]);
                split2(bv.x, bv.y, sBh[it], sBl[it]);
            }
        }
    };

    auto storeAB = [&](int buf) {
        __nv_bfloat16* Ah = smbuf + (size_t)buf * 4 * 128 * SST;
        __nv_bfloat16* Al = Ah + 128 * SST;
        __nv_bfloat16* Bh = Al + 128 * SST;
        __nv_bfloat16* Bl = Bh + 128 * SST;
        if (MODE == 2) {
#pragma unroll
            for (int it = 0; it < 8; it++) {
                int row = l2_r + 16 * it;
                *reinterpret_cast<unsigned*>(&Ah[row * SST + l2_p0]) = sAh[it];
                *reinterpret_cast<unsigned*>(&Al[row * SST + l2_p0]) = sAl[it];
                *reinterpret_cast<unsigned*>(&Bh[row * SST + l2_p0]) = sBh[it];
                *reinterpret_cast<unsigned*>(&Bl[row * SST + l2_p0]) = sBl[it];
            }
        } else {
#pragma unroll
            for (int u = 0; u < 8; u++) {
                *reinterpret_cast<unsigned*>(&Ah[la_m * SST + la_k0 + 2 * u]) = sAh[u];
                *reinterpret_cast<unsigned*>(&Al[la_m * SST + la_k0 + 2 * u]) = sAl[u];
                *reinterpret_cast<unsigned*>(&Bh[lb_n * SST + lb_k0 + 2 * u]) = sBh[u];
                *reinterpret_cast<unsigned*>(&Bl[lb_n * SST + lb_k0 + 2 * u]) = sBl[u];
            }
        }
    };

    loadA(0);
    loadB(0);
    for (int kt = 0; kt < KTOT; kt += 32) {
        const int buf = (kt >> 5) & 1;
        storeAB(buf);
        __syncthreads();
        if (kt + 32 < KTOT) { loadA(kt + 32); loadB(kt + 32); }

        const __nv_bfloat16* Ah = smbuf + (size_t)buf * 4 * 128 * SST;
        const __nv_bfloat16* Al = Ah + 128 * SST;
        const __nv_bfloat16* Bh = Al + 128 * SST;
        const __nv_bfloat16* Bl = Bh + 128 * SST;

#pragma unroll
        for (int ks = 0; ks < 2; ks++) {
            const int kk = ks * 16 + 2 * cq;
            unsigned bh[4][2], bl[4][2];
#pragma unroll
            for (int nt = 0; nt < 4; nt++) {
                int nr = (wn + nt * 8 + gq) * SST + kk;
                bh[nt][0] = *reinterpret_cast<const unsigned*>(&Bh[nr]);
                bh[nt][1] = *reinterpret_cast<const unsigned*>(&Bh[nr + 8]);
                bl[nt][0] = *reinterpret_cast<const unsigned*>(&Bl[nr]);
                bl[nt][1] = *reinterpret_cast<const unsigned*>(&Bl[nr + 8]);
            }
#pragma unroll
            for (int mt = 0; mt < 4; mt++) {
                int mr0 = (wm + mt * 16 + gq) * SST + kk;
                int mr1 = mr0 + 8 * SST;
                unsigned ah0 = *reinterpret_cast<const unsigned*>(&Ah[mr0]);
                unsigned ah1 = *reinterpret_cast<const unsigned*>(&Ah[mr1]);
                unsigned ah2 = *reinterpret_cast<const unsigned*>(&Ah[mr0 + 8]);
                unsigned ah3 = *reinterpret_cast<const unsigned*>(&Ah[mr1 + 8]);
                unsigned al0 = *reinterpret_cast<const unsigned*>(&Al[mr0]);
                unsigned al1 = *reinterpret_cast<const unsigned*>(&Al[mr1]);
                unsigned al2 = *reinterpret_cast<const unsigned*>(&Al[mr0 + 8]);
                unsigned al3 = *reinterpret_cast<const unsigned*>(&Al[mr1 + 8]);
#pragma unroll
                for (int nt = 0; nt < 4; nt++) {
                    float* a = acc[mt][nt];
                    mma_bf16(a[0], a[1], a[2], a[3], ah0, ah1, ah2, ah3, bh[nt][0], bh[nt][1]);
                    mma_bf16(a[0], a[1], a[2], a[3], ah0, ah1, ah2, ah3, bl[nt][0], bl[nt][1]);
                    mma_bf16(a[0], a[1], a[2], a[3], al0, al1, al2, al3, bh[nt][0], bh[nt][1]);
                }
            }
        }
        __syncthreads();
    }

    // ---- epilogue ----
    const float scale = (MODE == 3) ? 0.051031036307982884f : 1.0f;  // 1/sqrt(384)
#pragma unroll
    for (int mt = 0; mt < 4; mt++) {
#pragma unroll
        for (int nt = 0; nt < 4; nt++) {
            int m0 = wm + mt * 16 + gq;
            int m1 = m0 + 8;
            int col = wn + nt * 8 + 2 * cq;
            float2 v0 = make_float2(acc[mt][nt][0] * scale, acc[mt][nt][1] * scale);
            float2 v1 = make_float2(acc[mt][nt][2] * scale, acc[mt][nt][3] * scale);
            if (MODE == 2) {
                float* cb = g_t9p + ((size_t)blockIdx.z * NB + nb) * CH * K3 + nt0;
                *reinterpret_cast<float2*>(&cb[(size_t)m0 * K3 + col]) = v0;
                *reinterpret_cast<float2*>(&cb[(size_t)m1 * K3 + col]) = v1;
            } else {
                float* cb = Cdst + (size_t)nb * CH * PP + nt0;
                *reinterpret_cast<float2*>(&cb[(size_t)m0 * PP + col]) = v0;
                *reinterpret_cast<float2*>(&cb[(size_t)m1 * PP + col]) = v1;
            }
        }
    }
}

// ---------------------------------------------------------------------------
extern "C" void kernel_launch(void* const* d_in, const int* in_sizes, int n_in,
                              void* d_out, int out_size)
{
    const float* x   = (const float*)d_in[0];  // [N,C,H,W]
    const float* w3  = (const float*)d_in[1];  // [C,3C]
    const float* p5  = (const float*)d_in[2];  // [H,W]
    const float* w6  = (const float*)d_in[3];  // [C,C,3,1] -> [C,3C]
    const float* p8  = (const float*)d_in[4];  // [C]
    const float* p12 = (const float*)d_in[5];  // [3,H]
    float* out = (float*)d_out;

    // resolve device symbol addresses + opt into >48KB dynamic smem
    // (non-stream APIs; deterministic, capture-safe)
    float* t3p = nullptr; float* t6p = nullptr;
    cudaGetSymbolAddress((void**)&t3p, g_t3);
    cudaGetSymbolAddress((void**)&t6p, g_t6);
    cudaFuncSetAttribute(mma_gemm_kernel<0>, cudaFuncAttributeMaxDynamicSharedMemorySize, SMEM_BYTES);
    cudaFuncSetAttribute(mma_gemm_kernel<1>, cudaFuncAttributeMaxDynamicSharedMemorySize, SMEM_BYTES);
    cudaFuncSetAttribute(mma_gemm_kernel<2>, cudaFuncAttributeMaxDynamicSharedMemorySize, SMEM_BYTES);
    cudaFuncSetAttribute(mma_gemm_kernel<3>, cudaFuncAttributeMaxDynamicSharedMemorySize, SMEM_BYTES);

    t5_kernel<<<(NB * CH * PP) / 256, 256>>>(x, p5);
    mma_gemm_kernel<0><<<dim3(32, NB), 256, SMEM_BYTES>>>(x, w3, p8, p12, t3p);
    mma_gemm_kernel<1><<<dim3(32, NB), 256, SMEM_BYTES>>>(x, w6, p8, p12, t6p);
    mma_gemm_kernel<2><<<dim3(3, NB, SPLITS), 256, SMEM_BYTES>>>(x, w3, p8, p12, nullptr);
    reduce_t9_kernel<<<(NB * CH * K3) / 256, 256>>>();
    mma_gemm_kernel<3><<<dim3(32, NB), 256, SMEM_BYTES>>>(x, w3, p8, p12, out);
}

// round 5
// speedup vs baseline: 3.2054x; 1.7072x over previous
#include <cuda_runtime.h>
#include <cuda_bf16.h>

#define NB 32
#define CH 128
#define PP 4096        // H*W
#define K3 384         // 3*C
#define SPLITS 8       // split-K for t9 (over p)

#define SSTA 40        // smem stride for [row][k32] tiles (80B, 16B-aligned, LDSM-conflict-free)
#define SSTB 136       // smem stride for [k32][n128] tiles (272B)
#define A_ELEMS (128 * SSTA)          // 5120
#define B_ELEMS_KN (32 * SSTB)        // 4352 (modes 0/1/3)
#define B_ELEMS_NK (128 * SSTA)       // 5120 (mode 2)

// fp32 scratch
__device__ float g_t3 [NB * CH * PP];
__device__ float g_t6 [NB * CH * PP];
__device__ float g_t9p[SPLITS * NB * CH * K3];
// bf16 hi/lo pre-split operands
__device__ __nv_bfloat16 g_w3h[CH * K3],  g_w3l[CH * K3];
__device__ __nv_bfloat16 g_w6h[CH * K3],  g_w6l[CH * K3];
__device__ __nv_bfloat16 g_t1h [NB * 3 * CH * PP], g_t1l [NB * 3 * CH * PP];
__device__ __nv_bfloat16 g_t5sh[NB * 3 * CH * PP], g_t5sl[NB * 3 * CH * PP];
__device__ __nv_bfloat16 g_t7h [NB * CH * PP],     g_t7l [NB * CH * PP];
__device__ __nv_bfloat16 g_t12h[NB * K3 * PP],     g_t12l[NB * K3 * PP];
__device__ __nv_bfloat16 g_t9h [NB * CH * K3],     g_t9l [NB * CH * K3];

// ---------------------------------------------------------------------------
__device__ __forceinline__ void split2(float v0, float v1, unsigned& hi, unsigned& lo)
{
    __nv_bfloat16 h0 = __float2bfloat16(v0);
    __nv_bfloat16 h1 = __float2bfloat16(v1);
    __nv_bfloat16 l0 = __float2bfloat16(v0 - __bfloat162float(h0));
    __nv_bfloat16 l1 = __float2bfloat16(v1 - __bfloat162float(h1));
    __nv_bfloat162 hh = __halves2bfloat162(h0, h1);
    __nv_bfloat162 ll = __halves2bfloat162(l0, l1);
    hi = *reinterpret_cast<unsigned*>(&hh);
    lo = *reinterpret_cast<unsigned*>(&ll);
}

__device__ __forceinline__ void mma_bf16(float& d0, float& d1, float& d2, float& d3,
                                         unsigned a0, unsigned a1, unsigned a2, unsigned a3,
                                         unsigned b0, unsigned b1)
{
    asm volatile(
        "mma.sync.aligned.m16n8k16.row.col.f32.bf16.bf16.f32 "
        "{%0,%1,%2,%3},{%4,%5,%6,%7},{%8,%9},{%0,%1,%2,%3};\n"
        : "+f"(d0), "+f"(d1), "+f"(d2), "+f"(d3)
        : "r"(a0), "r"(a1), "r"(a2), "r"(a3), "r"(b0), "r"(b1));
}

__device__ __forceinline__ void ldsm4(unsigned& r0, unsigned& r1, unsigned& r2, unsigned& r3, unsigned a)
{
    asm volatile("ldmatrix.sync.aligned.m8n8.x4.shared.b16 {%0,%1,%2,%3},[%4];"
                 : "=r"(r0), "=r"(r1), "=r"(r2), "=r"(r3) : "r"(a));
}
__device__ __forceinline__ void ldsm4t(unsigned& r0, unsigned& r1, unsigned& r2, unsigned& r3, unsigned a)
{
    asm volatile("ldmatrix.sync.aligned.m8n8.x4.trans.shared.b16 {%0,%1,%2,%3},[%4];"
                 : "=r"(r0), "=r"(r1), "=r"(r2), "=r"(r3) : "r"(a));
}
__device__ __forceinline__ void cp16(unsigned d, const void* s)
{
    asm volatile("cp.async.ca.shared.global [%0], [%1], 16;" :: "r"(d), "l"(s));
}

// ---------------------------------------------------------------------------
// Prep kernels (elementwise, write pre-split bf16 hi/lo)
// ---------------------------------------------------------------------------
__global__ void prep_w_kernel(const float* __restrict__ w3, const float* __restrict__ w6)
{
    int i2 = (blockIdx.x * 256 + threadIdx.x) * 2;
    unsigned h, l;
    if (i2 < CH * K3) {
        split2(w3[i2], w3[i2 + 1], h, l);
        *reinterpret_cast<unsigned*>(&g_w3h[i2]) = h;
        *reinterpret_cast<unsigned*>(&g_w3l[i2]) = l;
    } else {
        int j = i2 - CH * K3;
        split2(w6[j], w6[j + 1], h, l);
        *reinterpret_cast<unsigned*>(&g_w6h[j]) = h;
        *reinterpret_cast<unsigned*>(&g_w6l[j]) = l;
    }
}

// t1[m][c][p] = x shifted by 2m-2 in w (zero pad)
__global__ void prep_t1_kernel(const float* __restrict__ x)
{
    int i2 = (blockIdx.x * 256 + threadIdx.x) * 2;
    int p = i2 & (PP - 1);
    int r = i2 >> 12;
    int c = r & 127; r >>= 7;
    int m = r % 3;
    int nb = r / 3;
    int w = p & 63;
    const float* xr = x + ((size_t)nb * CH + c) * PP + (p - w);
    float v[2];
#pragma unroll
    for (int e = 0; e < 2; e++) {
        int wq = w + e + 2 * m - 2;
        v[e] = (wq >= 0 && wq < 64) ? xr[wq] : 0.f;
    }
    unsigned h, l;
    split2(v[0], v[1], h, l);
    *reinterpret_cast<unsigned*>(&g_t1h[i2]) = h;
    *reinterpret_cast<unsigned*>(&g_t1l[i2]) = l;
}

// t5s[m][c][h][w] = t5[c][h+3m-3][w] where t5 = p5 * max3_w(x)
__global__ void prep_t5s_kernel(const float* __restrict__ x, const float* __restrict__ p5)
{
    int i2 = (blockIdx.x * 256 + threadIdx.x) * 2;
    int p = i2 & (PP - 1);
    int r = i2 >> 12;
    int c = r & 127; r >>= 7;
    int m = r % 3;
    int nb = r / 3;
    int w = p & 63;
    int h = p >> 6;
    int hp = h + 3 * m - 3;
    float v[2] = {0.f, 0.f};
    if (hp >= 0 && hp < 64) {
        const float* xr = x + ((size_t)nb * CH + c) * PP + hp * 64;
#pragma unroll
        for (int e = 0; e < 2; e++) {
            int we = w + e;
            float mx = xr[we];
            if (we >= 2) mx = fmaxf(mx, xr[we - 2]);
            if (we < 62) mx = fmaxf(mx, xr[we + 2]);
            v[e] = p5[hp * 64 + we] * mx;
        }
    }
    unsigned hh, ll;
    split2(v[0], v[1], hh, ll);
    *reinterpret_cast<unsigned*>(&g_t5sh[i2]) = hh;
    *reinterpret_cast<unsigned*>(&g_t5sl[i2]) = ll;
}

// t12[n][k][p] = p12[j,h] * max(t6, max(x,t6) + max(t3, t1_j))
__global__ void prep_t12_kernel(const float* __restrict__ x, const float* __restrict__ p12)
{
    int i2 = (blockIdx.x * 256 + threadIdx.x) * 2;
    int p = i2 & (PP - 1);
    int r = i2 >> 12;
    int k = r % K3;
    int nb = r / K3;
    int cp = k / 3;
    int j  = k - 3 * cp;
    int h = p >> 6;
    int w = p & 63;
    size_t base = ((size_t)nb * CH + cp) * PP + p;
    float sc = p12[j * 64 + h];
    float v[2];
#pragma unroll
    for (int e = 0; e < 2; e++) {
        float xv  = x[base + e];
        float t6v = g_t6[base + e];
        float t3v = g_t3[base + e];
        int wq = w + e + 2 * j - 2;
        float x1 = (wq >= 0 && wq < 64) ? x[base + e - (w + e) + wq] : 0.f;
        v[e] = sc * fmaxf(t6v, fmaxf(xv, t6v) + fmaxf(t3v, x1));
    }
    unsigned hh, ll;
    split2(v[0], v[1], hh, ll);
    *reinterpret_cast<unsigned*>(&g_t12h[i2]) = hh;
    *reinterpret_cast<unsigned*>(&g_t12l[i2]) = ll;
}

// reduce split-K partials -> t9 (scaled), pre-split to bf16
__global__ void reduce_t9s_kernel()
{
    int i2 = (blockIdx.x * 256 + threadIdx.x) * 2;
    float s0 = 0.f, s1 = 0.f;
#pragma unroll
    for (int u = 0; u < SPLITS; u++) {
        s0 += g_t9p[(size_t)u * NB * CH * K3 + i2];
        s1 += g_t9p[(size_t)u * NB * CH * K3 + i2 + 1];
    }
    s0 *= (1.0f / 64.0f);
    s1 *= (1.0f / 64.0f);
    unsigned h, l;
    split2(s0, s1, h, l);
    *reinterpret_cast<unsigned*>(&g_t9h[i2]) = h;
    *reinterpret_cast<unsigned*>(&g_t9l[i2]) = l;
}

// ---------------------------------------------------------------------------
// Tensor-core GEMM, pure cp.async loaders + ldmatrix.
//   MODE 0: t3  = w3 @ t1            (epilogue: fp32 t3)
//   MODE 1: t6  = w6 @ t5s           (epilogue: fp32 t6 + fused t7 split)
//   MODE 2: t9p = t7 @ t1^T slabs    (A,B both [row][k] layout)
//   MODE 3: out = t9 @ t12           (epilogue: scaled fp32 out)
// ---------------------------------------------------------------------------
template <int MODE>
__global__ void __launch_bounds__(256, 2)
mma_gemm_kernel(const float* __restrict__ x, const float* __restrict__ p8,
                float* __restrict__ Cdst)
{
    extern __shared__ __nv_bfloat16 smbuf[];
    const int B_ELEMS  = (MODE == 2) ? B_ELEMS_NK : B_ELEMS_KN;
    const int STAGE    = 2 * A_ELEMS + 2 * B_ELEMS;
    const int BH_OFF   = 2 * A_ELEMS;           // 10240
    const int KTOT     = (MODE == 2) ? (PP / SPLITS) : K3;
    const int nb       = blockIdx.y;
    const int nt0      = blockIdx.x * 128;
    const int kbase    = (MODE == 2) ? blockIdx.z * (PP / SPLITS) : 0;

    const int tid = threadIdx.x;
    const int wid = tid >> 5, lane = tid & 31;
    const int gq = lane >> 2, cq = lane & 3;
    const int lr = lane & 15;
    const int kh8 = (lane >> 4) * 8;
    const int wm = (wid >> 2) * 64, wn = (wid & 3) * 32;

    const unsigned sm0 = (unsigned)__cvta_generic_to_shared(smbuf);

    // A source (row-major [row][k])
    const __nv_bfloat16 *srcAh, *srcAl;
    int strideA;
    if (MODE == 0)      { srcAh = g_w3h; srcAl = g_w3l; strideA = K3; }
    else if (MODE == 1) { srcAh = g_w6h; srcAl = g_w6l; strideA = K3; }
    else if (MODE == 2) { srcAh = g_t7h + (size_t)nb * CH * PP + kbase;
                          srcAl = g_t7l + (size_t)nb * CH * PP + kbase; strideA = PP; }
    else                { srcAh = g_t9h + (size_t)nb * CH * K3;
                          srcAl = g_t9l + (size_t)nb * CH * K3; strideA = K3; }

    float acc[4][4][4];
#pragma unroll
    for (int i = 0; i < 4; i++)
#pragma unroll
        for (int j = 0; j < 4; j++)
#pragma unroll
            for (int q = 0; q < 4; q++) acc[i][j][q] = 0.f;

    auto issue_stage = [&](int kt, int buf) {
        const int sb = buf * STAGE;
        // A: 128 rows x 32 bf16; 512 chunks of 16B
#pragma unroll
        for (int q = 0; q < 2; q++) {
            int c = tid + q * 256;
            int row = c >> 2, off = (c & 3) * 8;
            unsigned d = sm0 + 2 * (sb + row * SSTA + off);
            cp16(d, srcAh + (size_t)row * strideA + kt + off);
            cp16(d + 2 * A_ELEMS, srcAl + (size_t)row * strideA + kt + off);
        }
        // B
        if (MODE == 2) {
            // rows = j (n), k = p : [n][k] layout
#pragma unroll
            for (int q = 0; q < 2; q++) {
                int c = tid + q * 256;
                int row = c >> 2, off = (c & 3) * 8;
                int j = nt0 + row;
                int cp = j / 3, m = j - 3 * cp;
                size_t gidx = (((size_t)nb * 3 + m) * CH + cp) * PP + kbase + kt + off;
                unsigned d = sm0 + 2 * (sb + BH_OFF + row * SSTA + off);
                cp16(d, g_t1h + gidx);
                cp16(d + 2 * B_ELEMS_NK, g_t1l + gidx);
            }
        } else {
            // rows = k, cols = p : [k][n] layout
#pragma unroll
            for (int q = 0; q < 2; q++) {
                int c = tid + q * 256;
                int row = c >> 4, off = (c & 15) * 8;
                int k = kt + row;
                size_t gidx;
                const __nv_bfloat16 *sh, *sl;
                if (MODE == 3) {
                    gidx = ((size_t)nb * K3 + k) * PP + nt0 + off;
                    sh = g_t12h; sl = g_t12l;
                } else {
                    int cp = k / 3, m = k - 3 * cp;
                    gidx = (((size_t)nb * 3 + m) * CH + cp) * PP + nt0 + off;
                    if (MODE == 0) { sh = g_t1h;  sl = g_t1l;  }
                    else           { sh = g_t5sh; sl = g_t5sl; }
                }
                unsigned d = sm0 + 2 * (sb + BH_OFF + row * SSTB + off);
                cp16(d, sh + gidx);
                cp16(d + 2 * B_ELEMS_KN, sl + gidx);
            }
        }
    };

    auto compute = [&](int buf) {
        const int sb = buf * STAGE;
#pragma unroll
        for (int ks = 0; ks < 2; ks++) {
            unsigned bh[4][2], bl[4][2];
            if (MODE == 2) {
#pragma unroll
                for (int q = 0; q < 2; q++) {
                    int nrow = wn + q * 16 + (lane & 7) + ((lane >> 4) & 1) * 8;
                    int kc = ((lane >> 3) & 1) * 8 + ks * 16;
                    unsigned a = sm0 + 2 * (sb + BH_OFF + nrow * SSTA + kc);
                    ldsm4(bh[2 * q][0], bh[2 * q][1], bh[2 * q + 1][0], bh[2 * q + 1][1], a);
                    ldsm4(bl[2 * q][0], bl[2 * q][1], bl[2 * q + 1][0], bl[2 * q + 1][1],
                          a + 2 * B_ELEMS_NK);
                }
            } else {
#pragma unroll
                for (int q = 0; q < 2; q++) {
                    unsigned a = sm0 + 2 * (sb + BH_OFF + (ks * 16 + lr) * SSTB + wn + q * 16 + kh8);
                    ldsm4t(bh[2 * q][0], bh[2 * q][1], bh[2 * q + 1][0], bh[2 * q + 1][1], a);
                    ldsm4t(bl[2 * q][0], bl[2 * q][1], bl[2 * q + 1][0], bl[2 * q + 1][1],
                           a + 2 * B_ELEMS_KN);
                }
            }
#pragma unroll
            for (int mt = 0; mt < 4; mt++) {
                unsigned aA = sm0 + 2 * (sb + (wm + mt * 16 + lr) * SSTA + kh8 + ks * 16);
                unsigned ah0, ah1, ah2, ah3, al0, al1, al2, al3;
                ldsm4(ah0, ah1, ah2, ah3, aA);
                ldsm4(al0, al1, al2, al3, aA + 2 * A_ELEMS);
#pragma unroll
                for (int nt = 0; nt < 4; nt++) {
                    float* a = acc[mt][nt];
                    mma_bf16(a[0], a[1], a[2], a[3], ah0, ah1, ah2, ah3, bh[nt][0], bh[nt][1]);
                    mma_bf16(a[0], a[1], a[2], a[3], ah0, ah1, ah2, ah3, bl[nt][0], bl[nt][1]);
                    mma_bf16(a[0], a[1], a[2], a[3], al0, al1, al2, al3, bh[nt][0], bh[nt][1]);
                }
            }
        }
    };

    const int nstages = KTOT / 32;
    issue_stage(0, 0);
    asm volatile("cp.async.commit_group;");
    for (int it = 0; it < nstages; ++it) {
        const int buf = it & 1;
        if (it + 1 < nstages) {
            issue_stage((it + 1) * 32, buf ^ 1);
            asm volatile("cp.async.commit_group;");
            asm volatile("cp.async.wait_group 1;");
        } else {
            asm volatile("cp.async.wait_group 0;");
        }
        __syncthreads();
        compute(buf);
        __syncthreads();
    }

    // ---- epilogue ----
    const float scale = (MODE == 3) ? 0.051031036307982884f : 1.0f;  // 1/sqrt(384)
#pragma unroll
    for (int mt = 0; mt < 4; mt++) {
#pragma unroll
        for (int nt = 0; nt < 4; nt++) {
            int m0 = wm + mt * 16 + gq;
            int m1 = m0 + 8;
            int col = wn + nt * 8 + 2 * cq;
            float2 v0 = make_float2(acc[mt][nt][0] * scale, acc[mt][nt][1] * scale);
            float2 v1 = make_float2(acc[mt][nt][2] * scale, acc[mt][nt][3] * scale);
            if (MODE == 2) {
                float* cb = g_t9p + ((size_t)blockIdx.z * NB + nb) * CH * K3 + nt0;
                *reinterpret_cast<float2*>(&cb[(size_t)m0 * K3 + col]) = v0;
                *reinterpret_cast<float2*>(&cb[(size_t)m1 * K3 + col]) = v1;
            } else {
                float* cb = Cdst + (size_t)nb * CH * PP + nt0;
                *reinterpret_cast<float2*>(&cb[(size_t)m0 * PP + col]) = v0;
                *reinterpret_cast<float2*>(&cb[(size_t)m1 * PP + col]) = v1;
                if (MODE == 1) {
                    // fused t7 = p8[c]*max(x, t6) -> bf16 hi/lo
                    size_t i0 = ((size_t)nb * CH + m0) * PP + nt0 + col;
                    size_t i1 = ((size_t)nb * CH + m1) * PP + nt0 + col;
                    unsigned h, l;
                    float s0 = p8[m0], s1 = p8[m1];
                    split2(s0 * fmaxf(x[i0], v0.x), s0 * fmaxf(x[i0 + 1], v0.y), h, l);
                    *reinterpret_cast<unsigned*>(&g_t7h[i0]) = h;
                    *reinterpret_cast<unsigned*>(&g_t7l[i0]) = l;
                    split2(s1 * fmaxf(x[i1], v1.x), s1 * fmaxf(x[i1 + 1], v1.y), h, l);
                    *reinterpret_cast<unsigned*>(&g_t7h[i1]) = h;
                    *reinterpret_cast<unsigned*>(&g_t7l[i1]) = l;
                }
            }
        }
    }
}

// ---------------------------------------------------------------------------
extern "C" void kernel_launch(void* const* d_in, const int* in_sizes, int n_in,
                              void* d_out, int out_size)
{
    const float* x   = (const float*)d_in[0];  // [N,C,H,W]
    const float* w3  = (const float*)d_in[1];  // [C,3C]
    const float* p5  = (const float*)d_in[2];  // [H,W]
    const float* w6  = (const float*)d_in[3];  // [C,C,3,1] -> [C,3C]
    const float* p8  = (const float*)d_in[4];  // [C]
    const float* p12 = (const float*)d_in[5];  // [3,H]
    float* out = (float*)d_out;

    float* t3p = nullptr; float* t6p = nullptr;
    cudaGetSymbolAddress((void**)&t3p, g_t3);
    cudaGetSymbolAddress((void**)&t6p, g_t6);

    const int SM01 = 2 * (2 * A_ELEMS + 2 * B_ELEMS_KN) * 2;  // 75776 B
    const int SM2  = 2 * (2 * A_ELEMS + 2 * B_ELEMS_NK) * 2;  // 81920 B
    cudaFuncSetAttribute(mma_gemm_kernel<0>, cudaFuncAttributeMaxDynamicSharedMemorySize, SM01);
    cudaFuncSetAttribute(mma_gemm_kernel<1>, cudaFuncAttributeMaxDynamicSharedMemorySize, SM01);
    cudaFuncSetAttribute(mma_gemm_kernel<2>, cudaFuncAttributeMaxDynamicSharedMemorySize, SM2);
    cudaFuncSetAttribute(mma_gemm_kernel<3>, cudaFuncAttributeMaxDynamicSharedMemorySize, SM01);

    prep_w_kernel<<<(2 * CH * K3 / 2) / 256, 256>>>(w3, w6);
    prep_t1_kernel<<<(NB * 3 * CH * PP / 2) / 256, 256>>>(x);
    prep_t5s_kernel<<<(NB * 3 * CH * PP / 2) / 256, 256>>>(x, p5);
    mma_gemm_kernel<0><<<dim3(32, NB), 256, SM01>>>(x, p8, t3p);          // t3
    mma_gemm_kernel<1><<<dim3(32, NB), 256, SM01>>>(x, p8, t6p);          // t6 + t7
    mma_gemm_kernel<2><<<dim3(3, NB, SPLITS), 256, SM2>>>(x, p8, nullptr); // t9 partials
    reduce_t9s_kernel<<<(NB * CH * K3 / 2) / 256, 256>>>();
    prep_t12_kernel<<<(NB * K3 * PP / 2) / 256, 256>>>(x, p12);
    mma_gemm_kernel<3><<<dim3(32, NB), 256, SM01>>>(x, p8, out);          // out
}

// round 6
// speedup vs baseline: 3.2950x; 1.0280x over previous
#include <cuda_runtime.h>
#include <cuda_fp16.h>

#define NB 32
#define CH 128
#define PP 4096        // H*W
#define K3 384         // 3*C
#define SPLITS 8       // split-K for t9 (over p)
#define XROW 80        // padded x row: [2 zero][64 data][2 zero][12 zero]

#define SSTA 40        // smem stride for [row][k32] tiles
#define SSTB 136       // smem stride for [k32][n128] tiles
#define A_ELEMS (128 * SSTA)          // 5120
#define B_ELEMS_KN (32 * SSTB)        // 4352 (modes 0/1/3)
#define B_ELEMS_NK (128 * SSTA)       // 5120 (mode 2)

// fp32 scratch
__device__ float g_t3 [NB * CH * PP];
__device__ float g_t6 [NB * CH * PP];
__device__ float g_t9p[SPLITS * NB * CH * K3];
// fp16 hi/lo pre-split operands
__device__ __half g_w3rh[CH * K3], g_w3rl[CH * K3];   // k' = m*128+cp reorder
__device__ __half g_w6rh[CH * K3], g_w6rl[CH * K3];
__device__ __half g_xph[NB * CH * 64 * XROW], g_xpl[NB * CH * 64 * XROW]; // padded x
__device__ __half g_t5h [NB * CH * PP], g_t5l [NB * CH * PP];
__device__ __half g_t7h [NB * CH * PP], g_t7l [NB * CH * PP];
__device__ __half g_t12h[NB * K3 * PP], g_t12l[NB * K3 * PP];
__device__ __half g_t9h [NB * CH * K3], g_t9l [NB * CH * K3];

// ---------------------------------------------------------------------------
__device__ __forceinline__ void split2h(float v0, float v1, unsigned& hi, unsigned& lo)
{
    __half h0 = __float2half(v0);
    __half h1 = __float2half(v1);
    __half l0 = __float2half(v0 - __half2float(h0));
    __half l1 = __float2half(v1 - __half2float(h1));
    __half2 hh = __halves2half2(h0, h1);
    __half2 ll = __halves2half2(l0, l1);
    hi = *reinterpret_cast<unsigned*>(&hh);
    lo = *reinterpret_cast<unsigned*>(&ll);
}

__device__ __forceinline__ void mma_f16(float& d0, float& d1, float& d2, float& d3,
                                        unsigned a0, unsigned a1, unsigned a2, unsigned a3,
                                        unsigned b0, unsigned b1)
{
    asm volatile(
        "mma.sync.aligned.m16n8k16.row.col.f32.f16.f16.f32 "
        "{%0,%1,%2,%3},{%4,%5,%6,%7},{%8,%9},{%0,%1,%2,%3};\n"
        : "+f"(d0), "+f"(d1), "+f"(d2), "+f"(d3)
        : "r"(a0), "r"(a1), "r"(a2), "r"(a3), "r"(b0), "r"(b1));
}

__device__ __forceinline__ void ldsm4(unsigned& r0, unsigned& r1, unsigned& r2, unsigned& r3, unsigned a)
{
    asm volatile("ldmatrix.sync.aligned.m8n8.x4.shared.b16 {%0,%1,%2,%3},[%4];"
                 : "=r"(r0), "=r"(r1), "=r"(r2), "=r"(r3) : "r"(a));
}
__device__ __forceinline__ void ldsm4t(unsigned& r0, unsigned& r1, unsigned& r2, unsigned& r3, unsigned a)
{
    asm volatile("ldmatrix.sync.aligned.m8n8.x4.trans.shared.b16 {%0,%1,%2,%3},[%4];"
                 : "=r"(r0), "=r"(r1), "=r"(r2), "=r"(r3) : "r"(a));
}
__device__ __forceinline__ void cp16(unsigned d, const void* s)
{
    asm volatile("cp.async.ca.shared.global [%0], [%1], 16;" :: "r"(d), "l"(s));
}
__device__ __forceinline__ void cp16z(unsigned d, const void* s, int sz)
{
    asm volatile("cp.async.ca.shared.global [%0], [%1], 16, %2;" :: "r"(d), "l"(s), "r"(sz));
}
__device__ __forceinline__ void cp4(unsigned d, const void* s)
{
    asm volatile("cp.async.ca.shared.global [%0], [%1], 4;" :: "r"(d), "l"(s));
}

// ---------------------------------------------------------------------------
// Prep kernels
// ---------------------------------------------------------------------------
// w3r[o][m*128+cp] = w3[o][3cp+m]; same gather shape for w6 ([O][I][3] flat).
__global__ void prep_w_kernel(const float* __restrict__ w3, const float* __restrict__ w6)
{
    int idx = blockIdx.x * 256 + threadIdx.x;
    int half_n = CH * K3 / 2;
    const float* src = (idx < half_n) ? w3 : w6;
    __half* dh = (idx < half_n) ? g_w3rh : g_w6rh;
    __half* dl = (idx < half_n) ? g_w3rl : g_w6rl;
    int i2 = (idx % half_n) * 2;
    int o = i2 / K3;
    int kp = i2 - o * K3;        // k' (even)
    int m = kp >> 7;
    int cp = kp & 127;
    float v0 = src[o * K3 + 3 * cp + m];
    float v1 = src[o * K3 + 3 * (cp + 1) + m];
    unsigned h, l;
    split2h(v0, v1, h, l);
    *reinterpret_cast<unsigned*>(&dh[i2]) = h;
    *reinterpret_cast<unsigned*>(&dl[i2]) = l;
}

// xpad[nb][c][h][2+w] = x (halos stay zero from static init; never overwritten)
__global__ void prep_xpad_kernel(const float* __restrict__ x)
{
    int i2 = (blockIdx.x * 256 + threadIdx.x) * 2;
    if (i2 >= NB * CH * PP) return;
    int w = i2 & 63;
    int rest = i2 >> 6;          // (nb*CH+c)*64 + h
    float v0 = x[i2], v1 = x[i2 + 1];
    unsigned h, l;
    split2h(v0, v1, h, l);
    size_t d = (size_t)rest * XROW + 2 + w;
    *reinterpret_cast<unsigned*>(&g_xph[d]) = h;
    *reinterpret_cast<unsigned*>(&g_xpl[d]) = l;
}

// t5 = p5 * max3_w(x)
__global__ void prep_t5_kernel(const float* __restrict__ x, const float* __restrict__ p5)
{
    int i2 = (blockIdx.x * 256 + threadIdx.x) * 2;
    if (i2 >= NB * CH * PP) return;
    int p = i2 & (PP - 1);
    int w = p & 63;
    const float* xr = x + (i2 - w);
    float v[2];
#pragma unroll
    for (int e = 0; e < 2; e++) {
        int we = w + e;
        float mx = xr[we];
        if (we >= 2) mx = fmaxf(mx, xr[we - 2]);
        if (we < 62) mx = fmaxf(mx, xr[we + 2]);
        v[e] = p5[(p & (PP - 1)) - w + we] * mx;
    }
    unsigned h, l;
    split2h(v[0], v[1], h, l);
    *reinterpret_cast<unsigned*>(&g_t5h[i2]) = h;
    *reinterpret_cast<unsigned*>(&g_t5l[i2]) = l;
}

// t12[n][k][p] = p12[j,h] * max(t6, max(x,t6) + max(t3, t1_j))
__global__ void prep_t12_kernel(const float* __restrict__ x, const float* __restrict__ p12)
{
    int i2 = (blockIdx.x * 256 + threadIdx.x) * 2;
    int p = i2 & (PP - 1);
    int r = i2 >> 12;
    int k = r % K3;
    int nb = r / K3;
    int cp = k / 3;
    int j  = k - 3 * cp;
    int h = p >> 6;
    int w = p & 63;
    size_t base = ((size_t)nb * CH + cp) * PP + p;
    float sc = p12[j * 64 + h];
    float v[2];
#pragma unroll
    for (int e = 0; e < 2; e++) {
        float xv  = x[base + e];
        float t6v = g_t6[base + e];
        float t3v = g_t3[base + e];
        int wq = w + e + 2 * j - 2;
        float x1 = (wq >= 0 && wq < 64) ? x[base + e - (w + e) + wq] : 0.f;
        v[e] = sc * fmaxf(t6v, fmaxf(xv, t6v) + fmaxf(t3v, x1));
    }
    unsigned hh, ll;
    split2h(v[0], v[1], hh, ll);
    *reinterpret_cast<unsigned*>(&g_t12h[i2]) = hh;
    *reinterpret_cast<unsigned*>(&g_t12l[i2]) = ll;
}

__global__ void reduce_t9s_kernel()
{
    int i2 = (blockIdx.x * 256 + threadIdx.x) * 2;
    float s0 = 0.f, s1 = 0.f;
#pragma unroll
    for (int u = 0; u < SPLITS; u++) {
        s0 += g_t9p[(size_t)u * NB * CH * K3 + i2];
        s1 += g_t9p[(size_t)u * NB * CH * K3 + i2 + 1];
    }
    unsigned h, l;
    split2h(s0 * (1.0f / 64.0f), s1 * (1.0f / 64.0f), h, l);
    *reinterpret_cast<unsigned*>(&g_t9h[i2]) = h;
    *reinterpret_cast<unsigned*>(&g_t9l[i2]) = l;
}

// ---------------------------------------------------------------------------
// Tensor-core GEMM (cp.async loaders + ldmatrix + m16n8k16 f16 hi/lo split)
//   MODE 0: t3  = w3r @ t1(from xpad)     m-major k order
//   MODE 1: t6  = w6r @ t5(h-shifted)     + fused t7 epilogue
//   MODE 2: t9p = t7 @ t1^T(from xpad)
//   MODE 3: out = t9 @ t12
// ---------------------------------------------------------------------------
template <int MODE>
__global__ void __launch_bounds__(256, 2)
mma_gemm_kernel(const float* __restrict__ x, const float* __restrict__ p8,
                float* __restrict__ Cdst)
{
    extern __shared__ __half smbuf[];
    const int B_ELEMS  = (MODE == 2) ? B_ELEMS_NK : B_ELEMS_KN;
    const int STAGE    = 2 * A_ELEMS + 2 * B_ELEMS;
    const int BH_OFF   = 2 * A_ELEMS;
    const int KTOT     = (MODE == 2) ? (PP / SPLITS) : K3;
    const int nb       = blockIdx.y;
    const int nt0      = blockIdx.x * 128;
    const int kbase    = (MODE == 2) ? blockIdx.z * (PP / SPLITS) : 0;

    const int tid = threadIdx.x;
    const int wid = tid >> 5, lane = tid & 31;
    const int gq = lane >> 2, cq = lane & 3;
    const int lr = lane & 15;
    const int kh8 = (lane >> 4) * 8;
    const int wm = (wid >> 2) * 64, wn = (wid & 3) * 32;
    const int h0 = nt0 >> 6;   // p-tile h rows: h0, h0+1 (modes 0/1/3)

    const unsigned sm0 = (unsigned)__cvta_generic_to_shared(smbuf);

    // A source (row-major [row][k'])
    const __half *srcAh, *srcAl;
    int strideA;
    if (MODE == 0)      { srcAh = g_w3rh; srcAl = g_w3rl; strideA = K3; }
    else if (MODE == 1) { srcAh = g_w6rh; srcAl = g_w6rl; strideA = K3; }
    else if (MODE == 2) { srcAh = g_t7h + (size_t)nb * CH * PP + kbase;
                          srcAl = g_t7l + (size_t)nb * CH * PP + kbase; strideA = PP; }
    else                { srcAh = g_t9h + (size_t)nb * CH * K3;
                          srcAl = g_t9l + (size_t)nb * CH * K3; strideA = K3; }

    // mode2 B: per-thread row decomposition (constant across slabs)
    int m2_cp = 0, m2_m = 0, m2_r = 0, m2_wd0 = 0;
    if (MODE == 2) {
        m2_r = tid >> 1; m2_wd0 = (tid & 1) * 8;
        int j = nt0 + m2_r;
        m2_cp = j / 3; m2_m = j - 3 * m2_cp;
    }
    // mode0 B: per-thread row/word base
    const int m0_r = tid >> 3, m0_wd0 = (tid & 7) * 8;

    float acc[4][4][4];
#pragma unroll
    for (int i = 0; i < 4; i++)
#pragma unroll
        for (int j = 0; j < 4; j++)
#pragma unroll
            for (int q = 0; q < 4; q++) acc[i][j][q] = 0.f;

    auto issue_stage = [&](int kt, int buf) {
        const int sb = buf * STAGE;
        // ---- A: 128 rows x 32 halfs, cp16 ----
#pragma unroll
        for (int q = 0; q < 2; q++) {
            int c = tid + q * 256;
            int row = c >> 2, off = (c & 3) * 8;
            unsigned d = sm0 + 2 * (sb + row * SSTA + off);
            cp16(d, srcAh + (size_t)row * strideA + kt + off);
            cp16(d + 2 * A_ELEMS, srcAl + (size_t)row * strideA + kt + off);
        }
        // ---- B ----
        if (MODE == 0) {
            // [k'][n]: 32 rows (cp), shift 2m-2 via xpad, cp4
            int m = kt >> 7, cp0 = kt & 127;
            int cp = cp0 + m0_r;
            size_t rowbase = ((size_t)(nb * CH + cp) * 64) * XROW + 2 * m;
#pragma unroll
            for (int u = 0; u < 8; u++) {
                int pe = 2 * (m0_wd0 + u);
                int h = h0 + (pe >> 6), w = pe & 63;
                size_t s = rowbase + (size_t)h * XROW + w;
                unsigned d = sm0 + 2 * (sb + BH_OFF + m0_r * SSTB + pe);
                cp4(d, g_xph + s);
                cp4(d + 2 * B_ELEMS_KN, g_xpl + s);
            }
        } else if (MODE == 1) {
            // [k'][n]: rows cp, whole-row h shift, cp16 with zfill
            int m = kt >> 7, cp0 = kt & 127;
#pragma unroll
            for (int u = 0; u < 2; u++) {
                int v = tid + u * 256;
                int r = v >> 4, ck = v & 15;
                int hc = ck >> 3, w8 = ck & 7;
                int cp = cp0 + r;
                int hp = h0 + 3 * m - 3 + hc;
                int valid = (hp >= 0 && hp < 64);
                int hpc = valid ? hp : 0;
                size_t s = (size_t)(nb * CH + cp) * PP + hpc * 64 + w8 * 8;
                unsigned d = sm0 + 2 * (sb + BH_OFF + r * SSTB + hc * 64 + w8 * 8);
                int sz = valid ? 16 : 0;
                cp16z(d, g_t5h + s, sz);
                cp16z(d + 2 * B_ELEMS_KN, g_t5l + s, sz);
            }
        } else if (MODE == 2) {
            // [n][k]: 128 j rows x 32 p, shift via xpad, cp4
            int p0 = kbase + kt;
            int hh = p0 >> 6, w0 = p0 & 63;
            size_t rowbase = ((size_t)(nb * CH + m2_cp) * 64 + hh) * XROW + 2 * m2_m + w0;
#pragma unroll
            for (int u = 0; u < 8; u++) {
                int pe = 2 * (m2_wd0 + u);
                size_t s = rowbase + pe;
                unsigned d = sm0 + 2 * (sb + BH_OFF + m2_r * SSTA + pe);
                cp4(d, g_xph + s);
                cp4(d + 2 * B_ELEMS_NK, g_xpl + s);
            }
        } else {
            // [k][n]: t12 pairs, cp16
#pragma unroll
            for (int q = 0; q < 2; q++) {
                int c = tid + q * 256;
                int row = c >> 4, off = (c & 15) * 8;
                size_t gidx = ((size_t)nb * K3 + kt + row) * PP + nt0 + off;
                unsigned d = sm0 + 2 * (sb + BH_OFF + row * SSTB + off);
                cp16(d, g_t12h + gidx);
                cp16(d + 2 * B_ELEMS_KN, g_t12l + gidx);
            }
        }
    };

    auto compute = [&](int buf) {
        const int sb = buf * STAGE;
#pragma unroll
        for (int ks = 0; ks < 2; ks++) {
            unsigned bh[4][2], bl[4][2];
            if (MODE == 2) {
#pragma unroll
                for (int q = 0; q < 2; q++) {
                    int nrow = wn + q * 16 + (lane & 7) + ((lane >> 4) & 1) * 8;
                    int kc = ((lane >> 3) & 1) * 8 + ks * 16;
                    unsigned a = sm0 + 2 * (sb + BH_OFF + nrow * SSTA + kc);
                    ldsm4(bh[2 * q][0], bh[2 * q][1], bh[2 * q + 1][0], bh[2 * q + 1][1], a);
                    ldsm4(bl[2 * q][0], bl[2 * q][1], bl[2 * q + 1][0], bl[2 * q + 1][1],
                          a + 2 * B_ELEMS_NK);
                }
            } else {
#pragma unroll
                for (int q = 0; q < 2; q++) {
                    unsigned a = sm0 + 2 * (sb + BH_OFF + (ks * 16 + lr) * SSTB + wn + q * 16 + kh8);
                    ldsm4t(bh[2 * q][0], bh[2 * q][1], bh[2 * q + 1][0], bh[2 * q + 1][1], a);
                    ldsm4t(bl[2 * q][0], bl[2 * q][1], bl[2 * q + 1][0], bl[2 * q + 1][1],
                           a + 2 * B_ELEMS_KN);
                }
            }
#pragma unroll
            for (int mt = 0; mt < 4; mt++) {
                unsigned aA = sm0 + 2 * (sb + (wm + mt * 16 + lr) * SSTA + kh8 + ks * 16);
                unsigned ah0, ah1, ah2, ah3, al0, al1, al2, al3;
                ldsm4(ah0, ah1, ah2, ah3, aA);
                ldsm4(al0, al1, al2, al3, aA + 2 * A_ELEMS);
#pragma unroll
                for (int nt = 0; nt < 4; nt++) {
                    float* a = acc[mt][nt];
                    mma_f16(a[0], a[1], a[2], a[3], ah0, ah1, ah2, ah3, bh[nt][0], bh[nt][1]);
                    mma_f16(a[0], a[1], a[2], a[3], ah0, ah1, ah2, ah3, bl[nt][0], bl[nt][1]);
                    mma_f16(a[0], a[1], a[2], a[3], al0, al1, al2, al3, bh[nt][0], bh[nt][1]);
                }
            }
        }
    };

    const int nstages = KTOT / 32;
    issue_stage(0, 0);
    asm volatile("cp.async.commit_group;");
    for (int it = 0; it < nstages; ++it) {
        const int buf = it & 1;
        if (it + 1 < nstages) {
            issue_stage((it + 1) * 32, buf ^ 1);
            asm volatile("cp.async.commit_group;");
            asm volatile("cp.async.wait_group 1;");
        } else {
            asm volatile("cp.async.wait_group 0;");
        }
        __syncthreads();
        compute(buf);
        __syncthreads();
    }

    // ---- epilogue ----
    const float scale = (MODE == 3) ? 0.051031036307982884f : 1.0f;  // 1/sqrt(384)
#pragma unroll
    for (int mt = 0; mt < 4; mt++) {
#pragma unroll
        for (int nt = 0; nt < 4; nt++) {
            int m0 = wm + mt * 16 + gq;
            int m1 = m0 + 8;
            int col = wn + nt * 8 + 2 * cq;
            float2 v0 = make_float2(acc[mt][nt][0] * scale, acc[mt][nt][1] * scale);
            float2 v1 = make_float2(acc[mt][nt][2] * scale, acc[mt][nt][3] * scale);
            if (MODE == 2) {
                float* cb = g_t9p + ((size_t)blockIdx.z * NB + nb) * CH * K3 + nt0;
                *reinterpret_cast<float2*>(&cb[(size_t)m0 * K3 + col]) = v0;
                *reinterpret_cast<float2*>(&cb[(size_t)m1 * K3 + col]) = v1;
            } else {
                float* cb = Cdst + (size_t)nb * CH * PP + nt0;
                *reinterpret_cast<float2*>(&cb[(size_t)m0 * PP + col]) = v0;
                *reinterpret_cast<float2*>(&cb[(size_t)m1 * PP + col]) = v1;
                if (MODE == 1) {
                    size_t i0 = ((size_t)nb * CH + m0) * PP + nt0 + col;
                    size_t i1 = ((size_t)nb * CH + m1) * PP + nt0 + col;
                    unsigned h, l;
                    float s0 = p8[m0], s1 = p8[m1];
                    split2h(s0 * fmaxf(x[i0], v0.x), s0 * fmaxf(x[i0 + 1], v0.y), h, l);
                    *reinterpret_cast<unsigned*>(&g_t7h[i0]) = h;
                    *reinterpret_cast<unsigned*>(&g_t7l[i0]) = l;
                    split2h(s1 * fmaxf(x[i1], v1.x), s1 * fmaxf(x[i1 + 1], v1.y), h, l);
                    *reinterpret_cast<unsigned*>(&g_t7h[i1]) = h;
                    *reinterpret_cast<unsigned*>(&g_t7l[i1]) = l;
                }
            }
        }
    }
}

// ---------------------------------------------------------------------------
extern "C" void kernel_launch(void* const* d_in, const int* in_sizes, int n_in,
                              void* d_out, int out_size)
{
    const float* x   = (const float*)d_in[0];  // [N,C,H,W]
    const float* w3  = (const float*)d_in[1];  // [C,3C]
    const float* p5  = (const float*)d_in[2];  // [H,W]
    const float* w6  = (const float*)d_in[3];  // [C,C,3,1]
    const float* p8  = (const float*)d_in[4];  // [C]
    const float* p12 = (const float*)d_in[5];  // [3,H]
    float* out = (float*)d_out;

    float* t3p = nullptr; float* t6p = nullptr;
    cudaGetSymbolAddress((void**)&t3p, g_t3);
    cudaGetSymbolAddress((void**)&t6p, g_t6);

    const int SM01 = 2 * (2 * A_ELEMS + 2 * B_ELEMS_KN) * 2;  // 75776 B
    const int SM2  = 2 * (2 * A_ELEMS + 2 * B_ELEMS_NK) * 2;  // 81920 B
    cudaFuncSetAttribute(mma_gemm_kernel<0>, cudaFuncAttributeMaxDynamicSharedMemorySize, SM01);
    cudaFuncSetAttribute(mma_gemm_kernel<1>, cudaFuncAttributeMaxDynamicSharedMemorySize, SM01);
    cudaFuncSetAttribute(mma_gemm_kernel<2>, cudaFuncAttributeMaxDynamicSharedMemorySize, SM2);
    cudaFuncSetAttribute(mma_gemm_kernel<3>, cudaFuncAttributeMaxDynamicSharedMemorySize, SM01);

    prep_w_kernel<<<(CH * K3) / 256, 256>>>(w3, w6);
    prep_xpad_kernel<<<(NB * CH * PP / 2) / 256, 256>>>(x);
    prep_t5_kernel<<<(NB * CH * PP / 2) / 256, 256>>>(x, p5);
    mma_gemm_kernel<0><<<dim3(32, NB), 256, SM01>>>(x, p8, t3p);            // t3
    mma_gemm_kernel<1><<<dim3(32, NB), 256, SM01>>>(x, p8, t6p);            // t6 + t7
    mma_gemm_kernel<2><<<dim3(3, NB, SPLITS), 256, SM2>>>(x, p8, nullptr);  // t9 partials
    reduce_t9s_kernel<<<(NB * CH * K3 / 2) / 256, 256>>>();
    prep_t12_kernel<<<(NB * K3 * PP / 2) / 256, 256>>>(x, p12);
    mma_gemm_kernel<3><<<dim3(32, NB), 256, SM01>>>(x, p8, out);            // out
}

// round 8
// speedup vs baseline: 3.5104x; 1.0654x over previous
#include <cuda_runtime.h>
#include <cuda_fp16.h>
#include <cstdint>

#define NB 32
#define CH 128
#define PP 4096        // H*W
#define K3 384         // 3*C  (k' = m*128 + cp  m-major order EVERYWHERE)
#define SPLITS 8       // split-K for t9 (over p)

// smem geometry
#define SSTA 40        // [row][k32] stride (halfs)
#define SSTB 136       // [k32][n128] stride (halfs)
#define A_ELEMS (128 * SSTA)
#define B_ELEMS_KN (32 * SSTB)

// fp32 scratch
__device__ float g_t3 [NB * CH * PP];
__device__ float g_t6 [NB * CH * PP];
__device__ float g_t9p[SPLITS * NB * CH * K3];
// fp16 hi/lo pre-split operands
__device__ __half g_w3rh[CH * K3], g_w3rl[CH * K3];
__device__ __half g_w6rh[CH * K3], g_w6rl[CH * K3];
__device__ __half g_t1h [NB * K3 * PP], g_t1l [NB * K3 * PP];   // t1m [nb][k'][p]
__device__ __half g_t5h [NB * CH * PP], g_t5l [NB * CH * PP];
__device__ __half g_t7h [NB * CH * PP], g_t7l [NB * CH * PP];
__device__ __half g_t12h[NB * K3 * PP], g_t12l[NB * K3 * PP];   // rows k'
__device__ __half g_t9h [NB * CH * K3], g_t9l [NB * CH * K3];   // cols k'

// ---------------------------------------------------------------------------
__device__ __forceinline__ void split2h(float v0, float v1, unsigned& hi, unsigned& lo)
{
    __half h0 = __float2half(v0);
    __half h1 = __float2half(v1);
    __half l0 = __float2half(v0 - __half2float(h0));
    __half l1 = __float2half(v1 - __half2float(h1));
    __half2 hh = __halves2half2(h0, h1);
    __half2 ll = __halves2half2(l0, l1);
    hi = *reinterpret_cast<unsigned*>(&hh);
    lo = *reinterpret_cast<unsigned*>(&ll);
}

__device__ __forceinline__ void mma_f16(float& d0, float& d1, float& d2, float& d3,
                                        unsigned a0, unsigned a1, unsigned a2, unsigned a3,
                                        unsigned b0, unsigned b1)
{
    asm volatile(
        "mma.sync.aligned.m16n8k16.row.col.f32.f16.f16.f32 "
        "{%0,%1,%2,%3},{%4,%5,%6,%7},{%8,%9},{%0,%1,%2,%3};\n"
        : "+f"(d0), "+f"(d1), "+f"(d2), "+f"(d3)
        : "r"(a0), "r"(a1), "r"(a2), "r"(a3), "r"(b0), "r"(b1));
}

__device__ __forceinline__ void ldsm4(unsigned& r0, unsigned& r1, unsigned& r2, unsigned& r3, unsigned a)
{
    asm volatile("ldmatrix.sync.aligned.m8n8.x4.shared.b16 {%0,%1,%2,%3},[%4];"
                 : "=r"(r0), "=r"(r1), "=r"(r2), "=r"(r3) : "r"(a));
}
__device__ __forceinline__ void ldsm4t(unsigned& r0, unsigned& r1, unsigned& r2, unsigned& r3, unsigned a)
{
    asm volatile("ldmatrix.sync.aligned.m8n8.x4.trans.shared.b16 {%0,%1,%2,%3},[%4];"
                 : "=r"(r0), "=r"(r1), "=r"(r2), "=r"(r3) : "r"(a));
}
__device__ __forceinline__ void cp16(unsigned d, const void* s)
{
    asm volatile("cp.async.ca.shared.global [%0], [%1], 16;" :: "r"(d), "l"(s));
}
__device__ __forceinline__ void cp16z(unsigned d, const void* s, int sz)
{
    asm volatile("cp.async.ca.shared.global [%0], [%1], 16, %2;" :: "r"(d), "l"(s), "r"(sz));
}

// ---------------------------------------------------------------------------
// Prep kernels
// ---------------------------------------------------------------------------
// w3r[o][m*128+cp] = w3[o][3cp+m]; same for w6 ([O][I][3] flat, k=3i+kh).
__global__ void prep_w_kernel(const float* __restrict__ w3, const float* __restrict__ w6)
{
    int idx = blockIdx.x * 256 + threadIdx.x;
    int half_n = CH * K3 / 2;
    const float* src = (idx < half_n) ? w3 : w6;
    __half* dh = (idx < half_n) ? g_w3rh : g_w6rh;
    __half* dl = (idx < half_n) ? g_w3rl : g_w6rl;
    int i2 = (idx % half_n) * 2;
    int o = i2 / K3;
    int kp = i2 - o * K3;
    int m = kp >> 7;
    int cp = kp & 127;
    float v0 = src[o * K3 + 3 * cp + m];
    float v1 = src[o * K3 + 3 * (cp + 1) + m];
    unsigned h, l;
    split2h(v0, v1, h, l);
    *reinterpret_cast<unsigned*>(&dh[i2]) = h;
    *reinterpret_cast<unsigned*>(&dl[i2]) = l;
}

// t1m[nb][k'=m*128+cp][p] = x[nb][cp][p + 2m-2] (zero pad in w)
__global__ void prep_t1m_kernel(const float* __restrict__ x)
{
    int i2 = (blockIdx.x * 256 + threadIdx.x) * 2;
    int p = i2 & (PP - 1);
    int r = i2 >> 12;            // nb*K3 + k'
    int kp = r % K3;
    int nb = r / K3;
    int m = kp >> 7, cp = kp & 127;
    int w = p & 63;
    const float* xr = x + (size_t)(nb * CH + cp) * PP + (p - w);
    int sh = 2 * m - 2;
    float v0 = ((unsigned)(w + sh)     < 64u) ? xr[w + sh]     : 0.f;
    float v1 = ((unsigned)(w + 1 + sh) < 64u) ? xr[w + 1 + sh] : 0.f;
    unsigned h, l;
    split2h(v0, v1, h, l);
    *reinterpret_cast<unsigned*>(&g_t1h[i2]) = h;
    *reinterpret_cast<unsigned*>(&g_t1l[i2]) = l;
}

// t5 = p5 * max3_w(x)
__global__ void prep_t5_kernel(const float* __restrict__ x, const float* __restrict__ p5)
{
    int i2 = (blockIdx.x * 256 + threadIdx.x) * 2;
    if (i2 >= NB * CH * PP) return;
    int p = i2 & (PP - 1);
    int w = p & 63;
    const float* xr = x + (i2 - w);
    float v[2];
#pragma unroll
    for (int e = 0; e < 2; e++) {
        int we = w + e;
        float mx = xr[we];
        if (we >= 2) mx = fmaxf(mx, xr[we - 2]);
        if (we < 62) mx = fmaxf(mx, xr[we + 2]);
        v[e] = p5[p - w + we] * mx;
    }
    unsigned h, l;
    split2h(v[0], v[1], h, l);
    *reinterpret_cast<unsigned*>(&g_t5h[i2]) = h;
    *reinterpret_cast<unsigned*>(&g_t5l[i2]) = l;
}

// t12[nb][k'=j*128+cp][p] = p12[j,h] * max(t6, max(x,t6) + max(t3, t1_j))
__global__ void prep_t12_kernel(const float* __restrict__ x, const float* __restrict__ p12)
{
    int i2 = (blockIdx.x * 256 + threadIdx.x) * 2;
    int p = i2 & (PP - 1);
    int r = i2 >> 12;
    int kp = r % K3;
    int nb = r / K3;
    int j  = kp >> 7;
    int cp = kp & 127;
    int h = p >> 6;
    int w = p & 63;
    size_t base = ((size_t)nb * CH + cp) * PP + p;
    float sc = p12[j * 64 + h];
    float v[2];
#pragma unroll
    for (int e = 0; e < 2; e++) {
        float xv  = x[base + e];
        float t6v = g_t6[base + e];
        float t3v = g_t3[base + e];
        int wq = w + e + 2 * j - 2;
        float x1 = ((unsigned)wq < 64u) ? x[base + e - (w + e) + wq] : 0.f;
        v[e] = sc * fmaxf(t6v, fmaxf(xv, t6v) + fmaxf(t3v, x1));
    }
    unsigned hh, ll;
    split2h(v[0], v[1], hh, ll);
    *reinterpret_cast<unsigned*>(&g_t12h[i2]) = hh;
    *reinterpret_cast<unsigned*>(&g_t12l[i2]) = ll;
}

__global__ void reduce_t9s_kernel()
{
    int i2 = (blockIdx.x * 256 + threadIdx.x) * 2;
    float s0 = 0.f, s1 = 0.f;
#pragma unroll
    for (int u = 0; u < SPLITS; u++) {
        s0 += g_t9p[(size_t)u * NB * CH * K3 + i2];
        s1 += g_t9p[(size_t)u * NB * CH * K3 + i2 + 1];
    }
    unsigned h, l;
    split2h(s0 * (1.0f / 64.0f), s1 * (1.0f / 64.0f), h, l);
    *reinterpret_cast<unsigned*>(&g_t9h[i2]) = h;
    *reinterpret_cast<unsigned*>(&g_t9l[i2]) = l;
}

// ---------------------------------------------------------------------------
// mma.sync GEMM (cp16-only loaders + ldmatrix, fp16 hi/lo split)
//   MODE 0: t3  = w3r @ t1m        K=384 (k' rows)
//   MODE 1: t6  = w6r @ t5(hshift) K=384  + fused t7 epilogue
//   MODE 2: t9p = t7 @ t1m^T       K=512 slab ([row][k] layout both sides)
//   MODE 3: out = t9  @ t12        K=384
// ---------------------------------------------------------------------------
template <int MODE>
__global__ void __launch_bounds__(256, 2)
mma_gemm_kernel(const float* __restrict__ x, const float* __restrict__ p8,
                float* __restrict__ Cdst)
{
    extern __shared__ __half smbuf[];
    const int B_ELEMS = (MODE == 2) ? A_ELEMS : B_ELEMS_KN;
    const int STAGE   = 2 * A_ELEMS + 2 * B_ELEMS;
    const int BH_OFF  = 2 * A_ELEMS;
    const int KTOT    = (MODE == 2) ? (PP / SPLITS) : K3;
    const int nb      = blockIdx.y;
    const int nt0     = blockIdx.x * 128;
    const int kbase   = (MODE == 2) ? blockIdx.z * (PP / SPLITS) : 0;

    const int tid = threadIdx.x;
    const int wid = tid >> 5, lane = tid & 31;
    const int gq = lane >> 2, cq = lane & 3;
    const int lr = lane & 15;
    const int kh8 = (lane >> 4) * 8;
    const int wm = (wid >> 2) * 64, wn = (wid & 3) * 32;
    const int h0 = nt0 >> 6;

    const unsigned sm0 = (unsigned)__cvta_generic_to_shared(smbuf);

    const __half *srcAh, *srcAl;
    int strideA;
    if (MODE == 0)      { srcAh = g_w3rh; srcAl = g_w3rl; strideA = K3; }
    else if (MODE == 1) { srcAh = g_w6rh; srcAl = g_w6rl; strideA = K3; }
    else if (MODE == 2) { srcAh = g_t7h + (size_t)nb * CH * PP + kbase;
                          srcAl = g_t7l + (size_t)nb * CH * PP + kbase; strideA = PP; }
    else                { srcAh = g_t9h + (size_t)nb * CH * K3;
                          srcAl = g_t9l + (size_t)nb * CH * K3; strideA = K3; }

    // mode2 B: rows j' at nt0, contiguous in p
    const __half* srcB2h = g_t1h + ((size_t)nb * K3 + nt0) * PP + kbase;
    const __half* srcB2l = g_t1l + ((size_t)nb * K3 + nt0) * PP + kbase;

    float acc[4][4][4];
#pragma unroll
    for (int i = 0; i < 4; i++)
#pragma unroll
        for (int j = 0; j < 4; j++)
#pragma unroll
            for (int q = 0; q < 4; q++) acc[i][j][q] = 0.f;

    auto issue_stage = [&](int kt, int buf) {
        const int sb = buf * STAGE;
        // A: 128 rows x 32 halfs
#pragma unroll
        for (int q = 0; q < 2; q++) {
            int c = tid + q * 256;
            int row = c >> 2, off = (c & 3) * 8;
            unsigned d = sm0 + 2 * (sb + row * SSTA + off);
            cp16(d, srcAh + (size_t)row * strideA + kt + off);
            cp16(d + 2 * A_ELEMS, srcAl + (size_t)row * strideA + kt + off);
        }
        // B
        if (MODE == 2) {
            // [n][k] 128 rows x 32 halfs (same geometry as A)
#pragma unroll
            for (int q = 0; q < 2; q++) {
                int c = tid + q * 256;
                int row = c >> 2, off = (c & 3) * 8;
                unsigned d = sm0 + 2 * (sb + BH_OFF + row * SSTA + off);
                cp16(d, srcB2h + (size_t)row * PP + kt + off);
                cp16(d + 2 * A_ELEMS, srcB2l + (size_t)row * PP + kt + off);
            }
        } else if (MODE == 1) {
            int m = kt >> 7, cp0 = kt & 127;
#pragma unroll
            for (int u = 0; u < 2; u++) {
                int v = tid + u * 256;
                int r = v >> 4, ck = v & 15;
                int hc = ck >> 3, w8 = ck & 7;
                int cp = cp0 + r;
                int hp = h0 + 3 * m - 3 + hc;
                int valid = (hp >= 0 && hp < 64);
                int hpc = valid ? hp : 0;
                size_t s = (size_t)(nb * CH + cp) * PP + hpc * 64 + w8 * 8;
                unsigned d = sm0 + 2 * (sb + BH_OFF + r * SSTB + hc * 64 + w8 * 8);
                int sz = valid ? 16 : 0;
                cp16z(d, g_t5h + s, sz);
                cp16z(d + 2 * B_ELEMS_KN, g_t5l + s, sz);
            }
        } else {
            const __half* sh = (MODE == 0) ? g_t1h : g_t12h;
            const __half* sl = (MODE == 0) ? g_t1l : g_t12l;
#pragma unroll
            for (int q = 0; q < 2; q++) {
                int c = tid + q * 256;
                int row = c >> 4, off = (c & 15) * 8;
                size_t gidx = ((size_t)nb * K3 + kt + row) * PP + nt0 + off;
                unsigned d = sm0 + 2 * (sb + BH_OFF + row * SSTB + off);
                cp16(d, sh + gidx);
                cp16(d + 2 * B_ELEMS_KN, sl + gidx);
            }
        }
    };

    auto compute = [&](int buf) {
        const int sb = buf * STAGE;
#pragma unroll
        for (int ks = 0; ks < 2; ks++) {
            unsigned bh[4][2], bl[4][2];
            if (MODE == 2) {
#pragma unroll
                for (int q = 0; q < 2; q++) {
                    int nrow = wn + q * 16 + (lane & 7) + ((lane >> 4) & 1) * 8;
                    int kc = ((lane >> 3) & 1) * 8 + ks * 16;
                    unsigned a = sm0 + 2 * (sb + BH_OFF + nrow * SSTA + kc);
                    ldsm4(bh[2 * q][0], bh[2 * q][1], bh[2 * q + 1][0], bh[2 * q + 1][1], a);
                    ldsm4(bl[2 * q][0], bl[2 * q][1], bl[2 * q + 1][0], bl[2 * q + 1][1],
                          a + 2 * A_ELEMS);
                }
            } else {
#pragma unroll
                for (int q = 0; q < 2; q++) {
                    unsigned a = sm0 + 2 * (sb + BH_OFF + (ks * 16 + lr) * SSTB + wn + q * 16 + kh8);
                    ldsm4t(bh[2 * q][0], bh[2 * q][1], bh[2 * q + 1][0], bh[2 * q + 1][1], a);
                    ldsm4t(bl[2 * q][0], bl[2 * q][1], bl[2 * q + 1][0], bl[2 * q + 1][1],
                           a + 2 * B_ELEMS_KN);
                }
            }
#pragma unroll
            for (int mt = 0; mt < 4; mt++) {
                unsigned aA = sm0 + 2 * (sb + (wm + mt * 16 + lr) * SSTA + kh8 + ks * 16);
                unsigned ah0, ah1, ah2, ah3, al0, al1, al2, al3;
                ldsm4(ah0, ah1, ah2, ah3, aA);
                ldsm4(al0, al1, al2, al3, aA + 2 * A_ELEMS);
#pragma unroll
                for (int nt = 0; nt < 4; nt++) {
                    float* a = acc[mt][nt];
                    mma_f16(a[0], a[1], a[2], a[3], ah0, ah1, ah2, ah3, bh[nt][0], bh[nt][1]);
                    mma_f16(a[0], a[1], a[2], a[3], ah0, ah1, ah2, ah3, bl[nt][0], bl[nt][1]);
                    mma_f16(a[0], a[1], a[2], a[3], al0, al1, al2, al3, bh[nt][0], bh[nt][1]);
                }
            }
        }
    };

    const int nstages = KTOT / 32;
    issue_stage(0, 0);
    asm volatile("cp.async.commit_group;");
    for (int it = 0; it < nstages; ++it) {
        const int buf = it & 1;
        if (it + 1 < nstages) {
            issue_stage((it + 1) * 32, buf ^ 1);
            asm volatile("cp.async.commit_group;");
            asm volatile("cp.async.wait_group 1;");
        } else {
            asm volatile("cp.async.wait_group 0;");
        }
        __syncthreads();
        compute(buf);
        __syncthreads();
    }

    const float scale = (MODE == 3) ? 0.051031036307982884f : 1.0f;
#pragma unroll
    for (int mt = 0; mt < 4; mt++) {
#pragma unroll
        for (int nt = 0; nt < 4; nt++) {
            int m0 = wm + mt * 16 + gq;
            int m1 = m0 + 8;
            int col = wn + nt * 8 + 2 * cq;
            float2 v0 = make_float2(acc[mt][nt][0] * scale, acc[mt][nt][1] * scale);
            float2 v1 = make_float2(acc[mt][nt][2] * scale, acc[mt][nt][3] * scale);
            if (MODE == 2) {
                float* cb = g_t9p + ((size_t)blockIdx.z * NB + nb) * CH * K3 + nt0;
                *reinterpret_cast<float2*>(&cb[(size_t)m0 * K3 + col]) = v0;
                *reinterpret_cast<float2*>(&cb[(size_t)m1 * K3 + col]) = v1;
            } else {
                float* cb = Cdst + (size_t)nb * CH * PP + nt0;
                *reinterpret_cast<float2*>(&cb[(size_t)m0 * PP + col]) = v0;
                *reinterpret_cast<float2*>(&cb[(size_t)m1 * PP + col]) = v1;
                if (MODE == 1) {
                    size_t i0 = ((size_t)nb * CH + m0) * PP + nt0 + col;
                    size_t i1 = ((size_t)nb * CH + m1) * PP + nt0 + col;
                    unsigned h, l;
                    float s0 = p8[m0], s1 = p8[m1];
                    split2h(s0 * fmaxf(x[i0], v0.x), s0 * fmaxf(x[i0 + 1], v0.y), h, l);
                    *reinterpret_cast<unsigned*>(&g_t7h[i0]) = h;
                    *reinterpret_cast<unsigned*>(&g_t7l[i0]) = l;
                    split2h(s1 * fmaxf(x[i1], v1.x), s1 * fmaxf(x[i1 + 1], v1.y), h, l);
                    *reinterpret_cast<unsigned*>(&g_t7h[i1]) = h;
                    *reinterpret_cast<unsigned*>(&g_t7l[i1]) = l;
                }
            }
        }
    }
}

// ---------------------------------------------------------------------------
extern "C" void kernel_launch(void* const* d_in, const int* in_sizes, int n_in,
                              void* d_out, int out_size)
{
    const float* x   = (const float*)d_in[0];
    const float* w3  = (const float*)d_in[1];
    const float* p5  = (const float*)d_in[2];
    const float* w6  = (const float*)d_in[3];
    const float* p8  = (const float*)d_in[4];
    const float* p12 = (const float*)d_in[5];
    float* out = (float*)d_out;

    float* t3p = nullptr; float* t6p = nullptr;
    cudaGetSymbolAddress((void**)&t3p, g_t3);
    cudaGetSymbolAddress((void**)&t6p, g_t6);

    const int SM01 = 2 * (2 * A_ELEMS + 2 * B_ELEMS_KN) * 2;  // 75776 B
    const int SM2  = 2 * (4 * A_ELEMS) * 2;                   // 81920 B
    cudaFuncSetAttribute(mma_gemm_kernel<0>, cudaFuncAttributeMaxDynamicSharedMemorySize, SM01);
    cudaFuncSetAttribute(mma_gemm_kernel<1>, cudaFuncAttributeMaxDynamicSharedMemorySize, SM01);
    cudaFuncSetAttribute(mma_gemm_kernel<2>, cudaFuncAttributeMaxDynamicSharedMemorySize, SM2);
    cudaFuncSetAttribute(mma_gemm_kernel<3>, cudaFuncAttributeMaxDynamicSharedMemorySize, SM01);

    prep_w_kernel<<<(CH * K3) / 256, 256>>>(w3, w6);
    prep_t1m_kernel<<<(NB * K3 * PP / 2) / 256, 256>>>(x);
    prep_t5_kernel<<<(NB * CH * PP / 2) / 256, 256>>>(x, p5);
    mma_gemm_kernel<0><<<dim3(32, NB), 256, SM01>>>(x, p8, t3p);            // t3
    mma_gemm_kernel<1><<<dim3(32, NB), 256, SM01>>>(x, p8, t6p);            // t6 + t7
    mma_gemm_kernel<2><<<dim3(3, NB, SPLITS), 256, SM2>>>(x, p8, nullptr);  // t9 partials
    reduce_t9s_kernel<<<(NB * CH * K3 / 2) / 256, 256>>>();
    prep_t12_kernel<<<(NB * K3 * PP / 2) / 256, 256>>>(x, p12);
    mma_gemm_kernel<3><<<dim3(32, NB), 256, SM01>>>(x, p8, out);            // out
}

// round 9
// speedup vs baseline: 3.7479x; 1.0677x over previous
#include <cuda_runtime.h>
#include <cuda_fp16.h>
#include <cstdint>

#define NB 32
#define CH 128
#define PP 4096        // H*W
#define K3 384         // 3*C  (k' = m*128 + cp m-major order everywhere)
#define SPLITS 8       // split-K for t9 (over p)

// smem geometry
#define SSTA 40        // [row][k32] stride (halfs)
#define SSTB 136       // [k32][n128] stride (halfs)
#define A_ELEMS (128 * SSTA)
#define B_ELEMS_KN (32 * SSTB)

// fp32 scratch
__device__ float g_t3 [NB * CH * PP];
__device__ float g_t6 [NB * CH * PP];
__device__ float g_t9p[SPLITS * NB * CH * K3];
// fp16 hi/lo pre-split operands
__device__ __half g_w3rh[CH * K3], g_w3rl[CH * K3];
__device__ __half g_w6rh[CH * K3], g_w6rl[CH * K3];
__device__ __half g_t1h [NB * K3 * PP], g_t1l [NB * K3 * PP];   // t1m [nb][k'][p]
__device__ __half g_t5h [NB * CH * PP], g_t5l [NB * CH * PP];
__device__ __half g_t7h [NB * CH * PP], g_t7l [NB * CH * PP];
__device__ __half g_t12h[NB * K3 * PP], g_t12l[NB * K3 * PP];   // rows k'
__device__ __half g_t9h [NB * CH * K3], g_t9l [NB * CH * K3];   // cols k'

// ---------------------------------------------------------------------------
__device__ __forceinline__ void split2h(float v0, float v1, unsigned& hi, unsigned& lo)
{
    __half h0 = __float2half(v0);
    __half h1 = __float2half(v1);
    __half l0 = __float2half(v0 - __half2float(h0));
    __half l1 = __float2half(v1 - __half2float(h1));
    __half2 hh = __halves2half2(h0, h1);
    __half2 ll = __halves2half2(l0, l1);
    hi = *reinterpret_cast<unsigned*>(&hh);
    lo = *reinterpret_cast<unsigned*>(&ll);
}

__device__ __forceinline__ void mma_f16(float& d0, float& d1, float& d2, float& d3,
                                        unsigned a0, unsigned a1, unsigned a2, unsigned a3,
                                        unsigned b0, unsigned b1)
{
    asm volatile(
        "mma.sync.aligned.m16n8k16.row.col.f32.f16.f16.f32 "
        "{%0,%1,%2,%3},{%4,%5,%6,%7},{%8,%9},{%0,%1,%2,%3};\n"
        : "+f"(d0), "+f"(d1), "+f"(d2), "+f"(d3)
        : "r"(a0), "r"(a1), "r"(a2), "r"(a3), "r"(b0), "r"(b1));
}

__device__ __forceinline__ void ldsm4(unsigned& r0, unsigned& r1, unsigned& r2, unsigned& r3, unsigned a)
{
    asm volatile("ldmatrix.sync.aligned.m8n8.x4.shared.b16 {%0,%1,%2,%3},[%4];"
                 : "=r"(r0), "=r"(r1), "=r"(r2), "=r"(r3) : "r"(a));
}
__device__ __forceinline__ void ldsm4t(unsigned& r0, unsigned& r1, unsigned& r2, unsigned& r3, unsigned a)
{
    asm volatile("ldmatrix.sync.aligned.m8n8.x4.trans.shared.b16 {%0,%1,%2,%3},[%4];"
                 : "=r"(r0), "=r"(r1), "=r"(r2), "=r"(r3) : "r"(a));
}
__device__ __forceinline__ void cp16(unsigned d, const void* s)
{
    asm volatile("cp.async.ca.shared.global [%0], [%1], 16;" :: "r"(d), "l"(s));
}
__device__ __forceinline__ void cp16z(unsigned d, const void* s, int sz)
{
    asm volatile("cp.async.ca.shared.global [%0], [%1], 16, %2;" :: "r"(d), "l"(s), "r"(sz));
}

// ---------------------------------------------------------------------------
// Prep kernels
// ---------------------------------------------------------------------------
__global__ void prep_w_kernel(const float* __restrict__ w3, const float* __restrict__ w6)
{
    int idx = blockIdx.x * 256 + threadIdx.x;
    int half_n = CH * K3 / 2;
    const float* src = (idx < half_n) ? w3 : w6;
    __half* dh = (idx < half_n) ? g_w3rh : g_w6rh;
    __half* dl = (idx < half_n) ? g_w3rl : g_w6rl;
    int i2 = (idx % half_n) * 2;
    int o = i2 / K3;
    int kp = i2 - o * K3;
    int m = kp >> 7;
    int cp = kp & 127;
    float v0 = src[o * K3 + 3 * cp + m];
    float v1 = src[o * K3 + 3 * (cp + 1) + m];
    unsigned h, l;
    split2h(v0, v1, h, l);
    *reinterpret_cast<unsigned*>(&dh[i2]) = h;
    *reinterpret_cast<unsigned*>(&dl[i2]) = l;
}

// t1m[nb][k'=m*128+cp][p] = x[nb][cp][p + 2m-2] (zero pad in w)
__global__ void prep_t1m_kernel(const float* __restrict__ x)
{
    int i2 = (blockIdx.x * 256 + threadIdx.x) * 2;
    int p = i2 & (PP - 1);
    int r = i2 >> 12;
    int kp = r % K3;
    int nb = r / K3;
    int m = kp >> 7, cp = kp & 127;
    int w = p & 63;
    const float* xr = x + (size_t)(nb * CH + cp) * PP + (p - w);
    int sh = 2 * m - 2;
    float v0 = ((unsigned)(w + sh)     < 64u) ? xr[w + sh]     : 0.f;
    float v1 = ((unsigned)(w + 1 + sh) < 64u) ? xr[w + 1 + sh] : 0.f;
    unsigned h, l;
    split2h(v0, v1, h, l);
    *reinterpret_cast<unsigned*>(&g_t1h[i2]) = h;
    *reinterpret_cast<unsigned*>(&g_t1l[i2]) = l;
}

// t5 = p5 * max3_w(x)
__global__ void prep_t5_kernel(const float* __restrict__ x, const float* __restrict__ p5)
{
    int i2 = (blockIdx.x * 256 + threadIdx.x) * 2;
    if (i2 >= NB * CH * PP) return;
    int p = i2 & (PP - 1);
    int w = p & 63;
    const float* xr = x + (i2 - w);
    float v[2];
#pragma unroll
    for (int e = 0; e < 2; e++) {
        int we = w + e;
        float mx = xr[we];
        if (we >= 2) mx = fmaxf(mx, xr[we - 2]);
        if (we < 62) mx = fmaxf(mx, xr[we + 2]);
        v[e] = p5[p - w + we] * mx;
    }
    unsigned h, l;
    split2h(v[0], v[1], h, l);
    *reinterpret_cast<unsigned*>(&g_t5h[i2]) = h;
    *reinterpret_cast<unsigned*>(&g_t5l[i2]) = l;
}

// t12[nb][k'=j*128+cp][p] = p12[j,h] * max(t6, max(x,t6) + max(t3, t1_j))
__global__ void prep_t12_kernel(const float* __restrict__ x, const float* __restrict__ p12)
{
    int i2 = (blockIdx.x * 256 + threadIdx.x) * 2;
    int p = i2 & (PP - 1);
    int r = i2 >> 12;
    int kp = r % K3;
    int nb = r / K3;
    int j  = kp >> 7;
    int cp = kp & 127;
    int h = p >> 6;
    int w = p & 63;
    size_t base = ((size_t)nb * CH + cp) * PP + p;
    float sc = p12[j * 64 + h];
    float v[2];
#pragma unroll
    for (int e = 0; e < 2; e++) {
        float xv  = x[base + e];
        float t6v = g_t6[base + e];
        float t3v = g_t3[base + e];
        int wq = w + e + 2 * j - 2;
        float x1 = ((unsigned)wq < 64u) ? x[base + e - (w + e) + wq] : 0.f;
        v[e] = sc * fmaxf(t6v, fmaxf(xv, t6v) + fmaxf(t3v, x1));
    }
    unsigned hh, ll;
    split2h(v[0], v[1], hh, ll);
    *reinterpret_cast<unsigned*>(&g_t12h[i2]) = hh;
    *reinterpret_cast<unsigned*>(&g_t12l[i2]) = ll;
}

__global__ void reduce_t9s_kernel()
{
    int i2 = (blockIdx.x * 256 + threadIdx.x) * 2;
    float s0 = 0.f, s1 = 0.f;
#pragma unroll
    for (int u = 0; u < SPLITS; u++) {
        s0 += g_t9p[(size_t)u * NB * CH * K3 + i2];
        s1 += g_t9p[(size_t)u * NB * CH * K3 + i2 + 1];
    }
    unsigned h, l;
    split2h(s0 * (1.0f / 64.0f), s1 * (1.0f / 64.0f), h, l);
    *reinterpret_cast<unsigned*>(&g_t9h[i2]) = h;
    *reinterpret_cast<unsigned*>(&g_t9l[i2]) = l;
}

// ---------------------------------------------------------------------------
// mma.sync GEMM — 128 threads (4 warps as 2m x 2n), warp tile 64x64.
//   MODE 0: t3  = w3r @ t1m        K=384, hi/lo split (3 MMA)
//   MODE 1: t6  = w6r @ t5(hshift) K=384, HI-ONLY (1 MMA) + fused t7 epilogue
//   MODE 2: t9p = t7 @ t1m^T       K=512 slab, [row][k] both sides, split
//   MODE 3: out = t9  @ t12        K=384, split
// ---------------------------------------------------------------------------
template <int MODE>
__global__ void __launch_bounds__(128, 2)
mma_gemm_kernel(const float* __restrict__ x, const float* __restrict__ p8,
                float* __restrict__ Cdst)
{
    extern __shared__ __half smbuf[];
    const int B_ELEMS = (MODE == 2) ? A_ELEMS : B_ELEMS_KN;
    const int STAGE   = 2 * A_ELEMS + 2 * B_ELEMS;
    const int BH_OFF  = 2 * A_ELEMS;
    const int KTOT    = (MODE == 2) ? (PP / SPLITS) : K3;
    const int nb      = blockIdx.y;
    const int nt0     = blockIdx.x * 128;
    const int kbase   = (MODE == 2) ? blockIdx.z * (PP / SPLITS) : 0;

    const int tid = threadIdx.x;
    const int wid = tid >> 5, lane = tid & 31;
    const int gq = lane >> 2, cq = lane & 3;
    const int lr = lane & 15;
    const int kh8 = (lane >> 4) * 8;
    const int wm = (wid >> 1) * 64, wn = (wid & 1) * 64;
    const int h0 = nt0 >> 6;

    const unsigned sm0 = (unsigned)__cvta_generic_to_shared(smbuf);

    const __half *srcAh, *srcAl;
    int strideA;
    if (MODE == 0)      { srcAh = g_w3rh; srcAl = g_w3rl; strideA = K3; }
    else if (MODE == 1) { srcAh = g_w6rh; srcAl = g_w6rl; strideA = K3; }
    else if (MODE == 2) { srcAh = g_t7h + (size_t)nb * CH * PP + kbase;
                          srcAl = g_t7l + (size_t)nb * CH * PP + kbase; strideA = PP; }
    else                { srcAh = g_t9h + (size_t)nb * CH * K3;
                          srcAl = g_t9l + (size_t)nb * CH * K3; strideA = K3; }

    const __half* srcB2h = g_t1h + ((size_t)nb * K3 + nt0) * PP + kbase;
    const __half* srcB2l = g_t1l + ((size_t)nb * K3 + nt0) * PP + kbase;

    float acc[4][8][4];
#pragma unroll
    for (int i = 0; i < 4; i++)
#pragma unroll
        for (int j = 0; j < 8; j++)
#pragma unroll
            for (int q = 0; q < 4; q++) acc[i][j][q] = 0.f;

    auto issue_stage = [&](int kt, int buf) {
        const int sb = buf * STAGE;
        // A: 128 rows x 32 halfs
#pragma unroll
        for (int q = 0; q < 4; q++) {
            int c = tid + q * 128;
            int row = c >> 2, off = (c & 3) * 8;
            unsigned d = sm0 + 2 * (sb + row * SSTA + off);
            cp16(d, srcAh + (size_t)row * strideA + kt + off);
            if (MODE != 1)
                cp16(d + 2 * A_ELEMS, srcAl + (size_t)row * strideA + kt + off);
        }
        // B
        if (MODE == 2) {
#pragma unroll
            for (int q = 0; q < 4; q++) {
                int c = tid + q * 128;
                int row = c >> 2, off = (c & 3) * 8;
                unsigned d = sm0 + 2 * (sb + BH_OFF + row * SSTA + off);
                cp16(d, srcB2h + (size_t)row * PP + kt + off);
                cp16(d + 2 * A_ELEMS, srcB2l + (size_t)row * PP + kt + off);
            }
        } else if (MODE == 1) {
            int m = kt >> 7, cp0 = kt & 127;
#pragma unroll
            for (int u = 0; u < 4; u++) {
                int v = tid + u * 128;
                int r = v >> 4, ck = v & 15;
                int hc = ck >> 3, w8 = ck & 7;
                int cp = cp0 + r;
                int hp = h0 + 3 * m - 3 + hc;
                int valid = (hp >= 0 && hp < 64);
                int hpc = valid ? hp : 0;
                size_t s = (size_t)(nb * CH + cp) * PP + hpc * 64 + w8 * 8;
                unsigned d = sm0 + 2 * (sb + BH_OFF + r * SSTB + hc * 64 + w8 * 8);
                cp16z(d, g_t5h + s, valid ? 16 : 0);
            }
        } else {
            const __half* sh = (MODE == 0) ? g_t1h : g_t12h;
            const __half* sl = (MODE == 0) ? g_t1l : g_t12l;
#pragma unroll
            for (int q = 0; q < 4; q++) {
                int c = tid + q * 128;
                int row = c >> 4, off = (c & 15) * 8;
                size_t gidx = ((size_t)nb * K3 + kt + row) * PP + nt0 + off;
                unsigned d = sm0 + 2 * (sb + BH_OFF + row * SSTB + off);
                cp16(d, sh + gidx);
                cp16(d + 2 * B_ELEMS_KN, sl + gidx);
            }
        }
    };

    auto compute = [&](int buf) {
        const int sb = buf * STAGE;
#pragma unroll
        for (int ks = 0; ks < 2; ks++) {
            unsigned bh[8][2], bl[8][2];
            if (MODE == 2) {
#pragma unroll
                for (int q = 0; q < 4; q++) {
                    int nrow = wn + q * 16 + (lane & 7) + ((lane >> 4) & 1) * 8;
                    int kc = ((lane >> 3) & 1) * 8 + ks * 16;
                    unsigned a = sm0 + 2 * (sb + BH_OFF + nrow * SSTA + kc);
                    ldsm4(bh[2 * q][0], bh[2 * q][1], bh[2 * q + 1][0], bh[2 * q + 1][1], a);
                    ldsm4(bl[2 * q][0], bl[2 * q][1], bl[2 * q + 1][0], bl[2 * q + 1][1],
                          a + 2 * A_ELEMS);
                }
            } else {
#pragma unroll
                for (int q = 0; q < 4; q++) {
                    unsigned a = sm0 + 2 * (sb + BH_OFF + (ks * 16 + lr) * SSTB + wn + q * 16 + kh8);
                    ldsm4t(bh[2 * q][0], bh[2 * q][1], bh[2 * q + 1][0], bh[2 * q + 1][1], a);
                    if (MODE != 1)
                        ldsm4t(bl[2 * q][0], bl[2 * q][1], bl[2 * q + 1][0], bl[2 * q + 1][1],
                               a + 2 * B_ELEMS_KN);
                }
            }
#pragma unroll
            for (int mt = 0; mt < 4; mt++) {
                unsigned aA = sm0 + 2 * (sb + (wm + mt * 16 + lr) * SSTA + kh8 + ks * 16);
                unsigned ah0, ah1, ah2, ah3, al0, al1, al2, al3;
                ldsm4(ah0, ah1, ah2, ah3, aA);
                if (MODE != 1) ldsm4(al0, al1, al2, al3, aA + 2 * A_ELEMS);
#pragma unroll
                for (int nt = 0; nt < 8; nt++) {
                    float* a = acc[mt][nt];
                    mma_f16(a[0], a[1], a[2], a[3], ah0, ah1, ah2, ah3, bh[nt][0], bh[nt][1]);
                    if (MODE != 1) {
                        mma_f16(a[0], a[1], a[2], a[3], ah0, ah1, ah2, ah3, bl[nt][0], bl[nt][1]);
                        mma_f16(a[0], a[1], a[2], a[3], al0, al1, al2, al3, bh[nt][0], bh[nt][1]);
                    }
                }
            }
        }
    };

    const int nstages = KTOT / 32;
    issue_stage(0, 0);
    asm volatile("cp.async.commit_group;");
    for (int it = 0; it < nstages; ++it) {
        const int buf = it & 1;
        if (it + 1 < nstages) {
            issue_stage((it + 1) * 32, buf ^ 1);
            asm volatile("cp.async.commit_group;");
            asm volatile("cp.async.wait_group 1;");
        } else {
            asm volatile("cp.async.wait_group 0;");
        }
        __syncthreads();
        compute(buf);
        __syncthreads();
    }

    const float scale = (MODE == 3) ? 0.051031036307982884f : 1.0f;
#pragma unroll
    for (int mt = 0; mt < 4; mt++) {
#pragma unroll
        for (int nt = 0; nt < 8; nt++) {
            int m0 = wm + mt * 16 + gq;
            int m1 = m0 + 8;
            int col = wn + nt * 8 + 2 * cq;
            float2 v0 = make_float2(acc[mt][nt][0] * scale, acc[mt][nt][1] * scale);
            float2 v1 = make_float2(acc[mt][nt][2] * scale, acc[mt][nt][3] * scale);
            if (MODE == 2) {
                float* cb = g_t9p + ((size_t)blockIdx.z * NB + nb) * CH * K3 + nt0;
                *reinterpret_cast<float2*>(&cb[(size_t)m0 * K3 + col]) = v0;
                *reinterpret_cast<float2*>(&cb[(size_t)m1 * K3 + col]) = v1;
            } else {
                float* cb = Cdst + (size_t)nb * CH * PP + nt0;
                *reinterpret_cast<float2*>(&cb[(size_t)m0 * PP + col]) = v0;
                *reinterpret_cast<float2*>(&cb[(size_t)m1 * PP + col]) = v1;
                if (MODE == 1) {
                    size_t i0 = ((size_t)nb * CH + m0) * PP + nt0 + col;
                    size_t i1 = ((size_t)nb * CH + m1) * PP + nt0 + col;
                    unsigned h, l;
                    float s0 = p8[m0], s1 = p8[m1];
                    split2h(s0 * fmaxf(x[i0], v0.x), s0 * fmaxf(x[i0 + 1], v0.y), h, l);
                    *reinterpret_cast<unsigned*>(&g_t7h[i0]) = h;
                    *reinterpret_cast<unsigned*>(&g_t7l[i0]) = l;
                    split2h(s1 * fmaxf(x[i1], v1.x), s1 * fmaxf(x[i1 + 1], v1.y), h, l);
                    *reinterpret_cast<unsigned*>(&g_t7h[i1]) = h;
                    *reinterpret_cast<unsigned*>(&g_t7l[i1]) = l;
                }
            }
        }
    }
}

// ---------------------------------------------------------------------------
extern "C" void kernel_launch(void* const* d_in, const int* in_sizes, int n_in,
                              void* d_out, int out_size)
{
    const float* x   = (const float*)d_in[0];
    const float* w3  = (const float*)d_in[1];
    const float* p5  = (const float*)d_in[2];
    const float* w6  = (const float*)d_in[3];
    const float* p8  = (const float*)d_in[4];
    const float* p12 = (const float*)d_in[5];
    float* out = (float*)d_out;

    float* t3p = nullptr; float* t6p = nullptr;
    cudaGetSymbolAddress((void**)&t3p, g_t3);
    cudaGetSymbolAddress((void**)&t6p, g_t6);

    const int SM01 = 2 * (2 * A_ELEMS + 2 * B_ELEMS_KN) * 2;  // 75776 B
    const int SM2  = 2 * (4 * A_ELEMS) * 2;                   // 81920 B
    cudaFuncSetAttribute(mma_gemm_kernel<0>, cudaFuncAttributeMaxDynamicSharedMemorySize, SM01);
    cudaFuncSetAttribute(mma_gemm_kernel<1>, cudaFuncAttributeMaxDynamicSharedMemorySize, SM01);
    cudaFuncSetAttribute(mma_gemm_kernel<2>, cudaFuncAttributeMaxDynamicSharedMemorySize, SM2);
    cudaFuncSetAttribute(mma_gemm_kernel<3>, cudaFuncAttributeMaxDynamicSharedMemorySize, SM01);

    prep_w_kernel<<<(CH * K3) / 256, 256>>>(w3, w6);
    prep_t1m_kernel<<<(NB * K3 * PP / 2) / 256, 256>>>(x);
    prep_t5_kernel<<<(NB * CH * PP / 2) / 256, 256>>>(x, p5);
    mma_gemm_kernel<0><<<dim3(32, NB), 128, SM01>>>(x, p8, t3p);            // t3
    mma_gemm_kernel<1><<<dim3(32, NB), 128, SM01>>>(x, p8, t6p);            // t6 + t7
    mma_gemm_kernel<2><<<dim3(3, NB, SPLITS), 128, SM2>>>(x, p8, nullptr);  // t9 partials
    reduce_t9s_kernel<<<(NB * CH * K3 / 2) / 256, 256>>>();
    prep_t12_kernel<<<(NB * K3 * PP / 2) / 256, 256>>>(x, p12);
    mma_gemm_kernel<3><<<dim3(32, NB), 128, SM01>>>(x, p8, out);            // out
}

// round 10
// speedup vs baseline: 4.8273x; 1.2880x over previous
#include <cuda_runtime.h>
#include <cuda_fp16.h>
#include <cstdint>

#define NB 32
#define CH 128
#define PP 4096        // H*W
#define K3 384         // 3*C  (k' = m*128 + cp m-major order everywhere)
#define SPLITS 4       // split-K for t9 (over p)

// smem geometry
#define SSTA 40        // [row][k32] stride (halfs)
#define SSTB 136       // [k32][n128] stride (halfs)
#define A_ELEMS (128 * SSTA)
#define B_ELEMS_KN (32 * SSTB)

// fp32 scratch
__device__ float g_t3 [NB * CH * PP];
__device__ float g_t6 [NB * CH * PP];
__device__ float g_t9p[SPLITS * NB * CH * K3];
// fp16 single operands
__device__ __half g_w3r[CH * K3];
__device__ __half g_w6r[CH * K3];
__device__ __half g_t1s[NB * K3 * PP];   // t1m [nb][k'][p]
__device__ __half g_t5s[NB * CH * PP];
__device__ __half g_t7s[NB * CH * PP];
// fp16 hi/lo split operands (final GEMM only)
__device__ __half g_t12h[NB * K3 * PP], g_t12l[NB * K3 * PP];   // rows k'
__device__ __half g_t9h [NB * CH * K3], g_t9l [NB * CH * K3];   // cols k'

// ---------------------------------------------------------------------------
__device__ __forceinline__ unsigned pack2h(float v0, float v1)
{
    __half2 hh = __halves2half2(__float2half(v0), __float2half(v1));
    return *reinterpret_cast<unsigned*>(&hh);
}
__device__ __forceinline__ void split2h(float v0, float v1, unsigned& hi, unsigned& lo)
{
    __half h0 = __float2half(v0);
    __half h1 = __float2half(v1);
    __half l0 = __float2half(v0 - __half2float(h0));
    __half l1 = __float2half(v1 - __half2float(h1));
    __half2 hh = __halves2half2(h0, h1);
    __half2 ll = __halves2half2(l0, l1);
    hi = *reinterpret_cast<unsigned*>(&hh);
    lo = *reinterpret_cast<unsigned*>(&ll);
}

__device__ __forceinline__ void mma_f16(float& d0, float& d1, float& d2, float& d3,
                                        unsigned a0, unsigned a1, unsigned a2, unsigned a3,
                                        unsigned b0, unsigned b1)
{
    asm volatile(
        "mma.sync.aligned.m16n8k16.row.col.f32.f16.f16.f32 "
        "{%0,%1,%2,%3},{%4,%5,%6,%7},{%8,%9},{%0,%1,%2,%3};\n"
        : "+f"(d0), "+f"(d1), "+f"(d2), "+f"(d3)
        : "r"(a0), "r"(a1), "r"(a2), "r"(a3), "r"(b0), "r"(b1));
}

__device__ __forceinline__ void ldsm4(unsigned& r0, unsigned& r1, unsigned& r2, unsigned& r3, unsigned a)
{
    asm volatile("ldmatrix.sync.aligned.m8n8.x4.shared.b16 {%0,%1,%2,%3},[%4];"
                 : "=r"(r0), "=r"(r1), "=r"(r2), "=r"(r3) : "r"(a));
}
__device__ __forceinline__ void ldsm4t(unsigned& r0, unsigned& r1, unsigned& r2, unsigned& r3, unsigned a)
{
    asm volatile("ldmatrix.sync.aligned.m8n8.x4.trans.shared.b16 {%0,%1,%2,%3},[%4];"
                 : "=r"(r0), "=r"(r1), "=r"(r2), "=r"(r3) : "r"(a));
}
__device__ __forceinline__ void cp16(unsigned d, const void* s)
{
    asm volatile("cp.async.ca.shared.global [%0], [%1], 16;" :: "r"(d), "l"(s));
}
__device__ __forceinline__ void cp16z(unsigned d, const void* s, int sz)
{
    asm volatile("cp.async.ca.shared.global [%0], [%1], 16, %2;" :: "r"(d), "l"(s), "r"(sz));
}

// ---------------------------------------------------------------------------
// Prep kernels
// ---------------------------------------------------------------------------
__global__ void prep_w_kernel(const float* __restrict__ w3, const float* __restrict__ w6)
{
    int idx = blockIdx.x * 256 + threadIdx.x;
    int half_n = CH * K3 / 2;
    const float* src = (idx < half_n) ? w3 : w6;
    __half* dh = (idx < half_n) ? g_w3r : g_w6r;
    int i2 = (idx % half_n) * 2;
    int o = i2 / K3;
    int kp = i2 - o * K3;
    int m = kp >> 7;
    int cp = kp & 127;
    *reinterpret_cast<unsigned*>(&dh[i2]) =
        pack2h(src[o * K3 + 3 * cp + m], src[o * K3 + 3 * (cp + 1) + m]);
}

// t1m[nb][k'=m*128+cp][p] = x[nb][cp][p + 2m-2] (zero pad in w)
__global__ void prep_t1m_kernel(const float* __restrict__ x)
{
    int i2 = (blockIdx.x * 256 + threadIdx.x) * 2;
    int p = i2 & (PP - 1);
    int r = i2 >> 12;
    int kp = r % K3;
    int nb = r / K3;
    int m = kp >> 7, cp = kp & 127;
    int w = p & 63;
    const float* xr = x + (size_t)(nb * CH + cp) * PP + (p - w);
    int sh = 2 * m - 2;
    float v0 = ((unsigned)(w + sh)     < 64u) ? xr[w + sh]     : 0.f;
    float v1 = ((unsigned)(w + 1 + sh) < 64u) ? xr[w + 1 + sh] : 0.f;
    *reinterpret_cast<unsigned*>(&g_t1s[i2]) = pack2h(v0, v1);
}

// t5 = p5 * max3_w(x)
__global__ void prep_t5_kernel(const float* __restrict__ x, const float* __restrict__ p5)
{
    int i2 = (blockIdx.x * 256 + threadIdx.x) * 2;
    if (i2 >= NB * CH * PP) return;
    int p = i2 & (PP - 1);
    int w = p & 63;
    const float* xr = x + (i2 - w);
    float v[2];
#pragma unroll
    for (int e = 0; e < 2; e++) {
        int we = w + e;
        float mx = xr[we];
        if (we >= 2) mx = fmaxf(mx, xr[we - 2]);
        if (we < 62) mx = fmaxf(mx, xr[we + 2]);
        v[e] = p5[p - w + we] * mx;
    }
    *reinterpret_cast<unsigned*>(&g_t5s[i2]) = pack2h(v[0], v[1]);
}

// t12[nb][k'=j*128+cp][p] = p12[j,h] * max(t6, max(x,t6) + max(t3, t1_j))
__global__ void prep_t12_kernel(const float* __restrict__ x, const float* __restrict__ p12)
{
    int i2 = (blockIdx.x * 256 + threadIdx.x) * 2;
    int p = i2 & (PP - 1);
    int r = i2 >> 12;
    int kp = r % K3;
    int nb = r / K3;
    int j  = kp >> 7;
    int cp = kp & 127;
    int h = p >> 6;
    int w = p & 63;
    size_t base = ((size_t)nb * CH + cp) * PP + p;
    float sc = p12[j * 64 + h];
    float v[2];
#pragma unroll
    for (int e = 0; e < 2; e++) {
        float xv  = x[base + e];
        float t6v = g_t6[base + e];
        float t3v = g_t3[base + e];
        int wq = w + e + 2 * j - 2;
        float x1 = ((unsigned)wq < 64u) ? x[base + e - (w + e) + wq] : 0.f;
        v[e] = sc * fmaxf(t6v, fmaxf(xv, t6v) + fmaxf(t3v, x1));
    }
    unsigned hh, ll;
    split2h(v[0], v[1], hh, ll);
    *reinterpret_cast<unsigned*>(&g_t12h[i2]) = hh;
    *reinterpret_cast<unsigned*>(&g_t12l[i2]) = ll;
}

__global__ void reduce_t9s_kernel()
{
    int i2 = (blockIdx.x * 256 + threadIdx.x) * 2;
    float s0 = 0.f, s1 = 0.f;
#pragma unroll
    for (int u = 0; u < SPLITS; u++) {
        s0 += g_t9p[(size_t)u * NB * CH * K3 + i2];
        s1 += g_t9p[(size_t)u * NB * CH * K3 + i2 + 1];
    }
    unsigned h, l;
    split2h(s0 * (1.0f / 64.0f), s1 * (1.0f / 64.0f), h, l);
    *reinterpret_cast<unsigned*>(&g_t9h[i2]) = h;
    *reinterpret_cast<unsigned*>(&g_t9l[i2]) = l;
}

// ---------------------------------------------------------------------------
// mma.sync GEMM — 128 threads (4 warps as 2m x 2n), warp tile 64x64.
//   MODE 0: t3  = w3r @ t1s        K=384,  single fp16 (1 MMA)
//   MODE 1: t6  = w6r @ t5s(hsh)   K=384,  single (1 MMA) + fused t7 epilogue
//   MODE 2: t9p = t7s @ t1s^T      K=1024 slab, single (1 MMA)
//   MODE 3: out = t9  @ t12        K=384,  hi/lo split (3 MMA)
// ---------------------------------------------------------------------------
template <int MODE>
__global__ void __launch_bounds__(128, 2)
mma_gemm_kernel(const float* __restrict__ x, const float* __restrict__ p8,
                float* __restrict__ Cdst)
{
    extern __shared__ __half smbuf[];
    constexpr bool SPLIT = (MODE == 3);
    constexpr int B_EL   = (MODE == 2) ? A_ELEMS : B_ELEMS_KN;
    constexpr int A_SZ   = (SPLIT ? 2 : 1) * A_ELEMS;
    constexpr int B_SZ   = (SPLIT ? 2 : 1) * B_EL;
    constexpr int STAGE  = A_SZ + B_SZ;
    constexpr int BH_OFF = A_SZ;
    const int KTOT    = (MODE == 2) ? (PP / SPLITS) : K3;
    const int nb      = blockIdx.y;
    const int nt0     = blockIdx.x * 128;
    const int kbase   = (MODE == 2) ? blockIdx.z * (PP / SPLITS) : 0;

    const int tid = threadIdx.x;
    const int wid = tid >> 5, lane = tid & 31;
    const int gq = lane >> 2, cq = lane & 3;
    const int lr = lane & 15;
    const int kh8 = (lane >> 4) * 8;
    const int wm = (wid >> 1) * 64, wn = (wid & 1) * 64;
    const int h0 = nt0 >> 6;

    const unsigned sm0 = (unsigned)__cvta_generic_to_shared(smbuf);

    const __half *srcAh = nullptr, *srcAl = nullptr;
    int strideA;
    if (MODE == 0)      { srcAh = g_w3r; strideA = K3; }
    else if (MODE == 1) { srcAh = g_w6r; strideA = K3; }
    else if (MODE == 2) { srcAh = g_t7s + (size_t)nb * CH * PP + kbase; strideA = PP; }
    else                { srcAh = g_t9h + (size_t)nb * CH * K3;
                          srcAl = g_t9l + (size_t)nb * CH * K3; strideA = K3; }

    const __half* srcB2 = g_t1s + ((size_t)nb * K3 + nt0) * PP + kbase;

    float acc[4][8][4];
#pragma unroll
    for (int i = 0; i < 4; i++)
#pragma unroll
        for (int j = 0; j < 8; j++)
#pragma unroll
            for (int q = 0; q < 4; q++) acc[i][j][q] = 0.f;

    auto issue_stage = [&](int kt, int buf) {
        const int sb = buf * STAGE;
        // A: 128 rows x 32 halfs
#pragma unroll
        for (int q = 0; q < 4; q++) {
            int c = tid + q * 128;
            int row = c >> 2, off = (c & 3) * 8;
            unsigned d = sm0 + 2 * (sb + row * SSTA + off);
            cp16(d, srcAh + (size_t)row * strideA + kt + off);
            if (SPLIT)
                cp16(d + 2 * A_ELEMS, srcAl + (size_t)row * strideA + kt + off);
        }
        // B
        if (MODE == 2) {
#pragma unroll
            for (int q = 0; q < 4; q++) {
                int c = tid + q * 128;
                int row = c >> 2, off = (c & 3) * 8;
                unsigned d = sm0 + 2 * (sb + BH_OFF + row * SSTA + off);
                cp16(d, srcB2 + (size_t)row * PP + kt + off);
            }
        } else if (MODE == 1) {
            int m = kt >> 7, cp0 = kt & 127;
#pragma unroll
            for (int u = 0; u < 4; u++) {
                int v = tid + u * 128;
                int r = v >> 4, ck = v & 15;
                int hc = ck >> 3, w8 = ck & 7;
                int cp = cp0 + r;
                int hp = h0 + 3 * m - 3 + hc;
                int valid = (hp >= 0 && hp < 64);
                int hpc = valid ? hp : 0;
                size_t s = (size_t)(nb * CH + cp) * PP + hpc * 64 + w8 * 8;
                unsigned d = sm0 + 2 * (sb + BH_OFF + r * SSTB + hc * 64 + w8 * 8);
                cp16z(d, g_t5s + s, valid ? 16 : 0);
            }
        } else if (MODE == 0) {
#pragma unroll
            for (int q = 0; q < 4; q++) {
                int c = tid + q * 128;
                int row = c >> 4, off = (c & 15) * 8;
                size_t gidx = ((size_t)nb * K3 + kt + row) * PP + nt0 + off;
                unsigned d = sm0 + 2 * (sb + BH_OFF + row * SSTB + off);
                cp16(d, g_t1s + gidx);
            }
        } else { // MODE 3
#pragma unroll
            for (int q = 0; q < 4; q++) {
                int c = tid + q * 128;
                int row = c >> 4, off = (c & 15) * 8;
                size_t gidx = ((size_t)nb * K3 + kt + row) * PP + nt0 + off;
                unsigned d = sm0 + 2 * (sb + BH_OFF + row * SSTB + off);
                cp16(d, g_t12h + gidx);
                cp16(d + 2 * B_ELEMS_KN, g_t12l + gidx);
            }
        }
    };

    auto compute = [&](int buf) {
        const int sb = buf * STAGE;
#pragma unroll
        for (int ks = 0; ks < 2; ks++) {
            unsigned bh[8][2], bl[8][2];
            if (MODE == 2) {
#pragma unroll
                for (int q = 0; q < 4; q++) {
                    int nrow = wn + q * 16 + (lane & 7) + ((lane >> 4) & 1) * 8;
                    int kc = ((lane >> 3) & 1) * 8 + ks * 16;
                    unsigned a = sm0 + 2 * (sb + BH_OFF + nrow * SSTA + kc);
                    ldsm4(bh[2 * q][0], bh[2 * q][1], bh[2 * q + 1][0], bh[2 * q + 1][1], a);
                }
            } else {
#pragma unroll
                for (int q = 0; q < 4; q++) {
                    unsigned a = sm0 + 2 * (sb + BH_OFF + (ks * 16 + lr) * SSTB + wn + q * 16 + kh8);
                    ldsm4t(bh[2 * q][0], bh[2 * q][1], bh[2 * q + 1][0], bh[2 * q + 1][1], a);
                    if (SPLIT)
                        ldsm4t(bl[2 * q][0], bl[2 * q][1], bl[2 * q + 1][0], bl[2 * q + 1][1],
                               a + 2 * B_ELEMS_KN);
                }
            }
#pragma unroll
            for (int mt = 0; mt < 4; mt++) {
                unsigned aA = sm0 + 2 * (sb + (wm + mt * 16 + lr) * SSTA + kh8 + ks * 16);
                unsigned ah0, ah1, ah2, ah3, al0, al1, al2, al3;
                ldsm4(ah0, ah1, ah2, ah3, aA);
                if (SPLIT) ldsm4(al0, al1, al2, al3, aA + 2 * A_ELEMS);
#pragma unroll
                for (int nt = 0; nt < 8; nt++) {
                    float* a = acc[mt][nt];
                    mma_f16(a[0], a[1], a[2], a[3], ah0, ah1, ah2, ah3, bh[nt][0], bh[nt][1]);
                    if (SPLIT) {
                        mma_f16(a[0], a[1], a[2], a[3], ah0, ah1, ah2, ah3, bl[nt][0], bl[nt][1]);
                        mma_f16(a[0], a[1], a[2], a[3], al0, al1, al2, al3, bh[nt][0], bh[nt][1]);
                    }
                }
            }
        }
    };

    const int nstages = KTOT / 32;
    issue_stage(0, 0);
    asm volatile("cp.async.commit_group;");
    for (int it = 0; it < nstages; ++it) {
        const int buf = it & 1;
        if (it + 1 < nstages) {
            issue_stage((it + 1) * 32, buf ^ 1);
            asm volatile("cp.async.commit_group;");
            asm volatile("cp.async.wait_group 1;");
        } else {
            asm volatile("cp.async.wait_group 0;");
        }
        __syncthreads();
        compute(buf);
        __syncthreads();
    }

    const float scale = (MODE == 3) ? 0.051031036307982884f : 1.0f;
#pragma unroll
    for (int mt = 0; mt < 4; mt++) {
#pragma unroll
        for (int nt = 0; nt < 8; nt++) {
            int m0 = wm + mt * 16 + gq;
            int m1 = m0 + 8;
            int col = wn + nt * 8 + 2 * cq;
            float2 v0 = make_float2(acc[mt][nt][0] * scale, acc[mt][nt][1] * scale);
            float2 v1 = make_float2(acc[mt][nt][2] * scale, acc[mt][nt][3] * scale);
            if (MODE == 2) {
                float* cb = g_t9p + ((size_t)blockIdx.z * NB + nb) * CH * K3 + nt0;
                *reinterpret_cast<float2*>(&cb[(size_t)m0 * K3 + col]) = v0;
                *reinterpret_cast<float2*>(&cb[(size_t)m1 * K3 + col]) = v1;
            } else {
                float* cb = Cdst + (size_t)nb * CH * PP + nt0;
                *reinterpret_cast<float2*>(&cb[(size_t)m0 * PP + col]) = v0;
                *reinterpret_cast<float2*>(&cb[(size_t)m1 * PP + col]) = v1;
                if (MODE == 1) {
                    size_t i0 = ((size_t)nb * CH + m0) * PP + nt0 + col;
                    size_t i1 = ((size_t)nb * CH + m1) * PP + nt0 + col;
                    float s0 = p8[m0], s1 = p8[m1];
                    *reinterpret_cast<unsigned*>(&g_t7s[i0]) =
                        pack2h(s0 * fmaxf(x[i0], v0.x), s0 * fmaxf(x[i0 + 1], v0.y));
                    *reinterpret_cast<unsigned*>(&g_t7s[i1]) =
                        pack2h(s1 * fmaxf(x[i1], v1.x), s1 * fmaxf(x[i1 + 1], v1.y));
                }
            }
        }
    }
}

// ---------------------------------------------------------------------------
extern "C" void kernel_launch(void* const* d_in, const int* in_sizes, int n_in,
                              void* d_out, int out_size)
{
    const float* x   = (const float*)d_in[0];
    const float* w3  = (const float*)d_in[1];
    const float* p5  = (const float*)d_in[2];
    const float* w6  = (const float*)d_in[3];
    const float* p8  = (const float*)d_in[4];
    const float* p12 = (const float*)d_in[5];
    float* out = (float*)d_out;

    float* t3p = nullptr; float* t6p = nullptr;
    cudaGetSymbolAddress((void**)&t3p, g_t3);
    cudaGetSymbolAddress((void**)&t6p, g_t6);

    const int SM0 = 2 * (A_ELEMS + B_ELEMS_KN) * 2;       // 37,888 B
    const int SM2 = 2 * (2 * A_ELEMS) * 2;                // 40,960 B
    const int SM3 = 2 * (2 * A_ELEMS + 2 * B_ELEMS_KN) * 2;  // 75,776 B
    cudaFuncSetAttribute(mma_gemm_kernel<0>, cudaFuncAttributeMaxDynamicSharedMemorySize, SM0);
    cudaFuncSetAttribute(mma_gemm_kernel<1>, cudaFuncAttributeMaxDynamicSharedMemorySize, SM0);
    cudaFuncSetAttribute(mma_gemm_kernel<2>, cudaFuncAttributeMaxDynamicSharedMemorySize, SM2);
    cudaFuncSetAttribute(mma_gemm_kernel<3>, cudaFuncAttributeMaxDynamicSharedMemorySize, SM3);

    prep_w_kernel<<<(CH * K3) / 256, 256>>>(w3, w6);
    prep_t1m_kernel<<<(NB * K3 * PP / 2) / 256, 256>>>(x);
    prep_t5_kernel<<<(NB * CH * PP / 2) / 256, 256>>>(x, p5);
    mma_gemm_kernel<0><<<dim3(32, NB), 128, SM0>>>(x, p8, t3p);             // t3
    mma_gemm_kernel<1><<<dim3(32, NB), 128, SM0>>>(x, p8, t6p);             // t6 + t7
    mma_gemm_kernel<2><<<dim3(3, NB, SPLITS), 128, SM2>>>(x, p8, nullptr);  // t9 partials
    reduce_t9s_kernel<<<(NB * CH * K3 / 2) / 256, 256>>>();
    prep_t12_kernel<<<(NB * K3 * PP / 2) / 256, 256>>>(x, p12);
    mma_gemm_kernel<3><<<dim3(32, NB), 128, SM3>>>(x, p8, out);             // out
}

// round 11
// speedup vs baseline: 5.6359x; 1.1675x over previous
#include <cuda_runtime.h>
#include <cuda_fp16.h>
#include <cstdint>

#define NB 32
#define CH 128
#define PP 4096        // H*W
#define K3 384         // 3*C  (k' = m*128 + cp m-major order everywhere)
#define SPLITS 4       // split-K for t9 (over p)

// smem geometry
#define SSTA 40        // [row][k32] stride (halfs)
#define SSTB 136       // [k32][n128] stride (halfs)
#define A_ELEMS (128 * SSTA)
#define B_ELEMS_KN (32 * SSTB)

// fp32 scratch (split-K partials only)
__device__ float g_t9p[SPLITS * NB * CH * K3];
// fp16 single operands everywhere
__device__ __half g_w3r[CH * K3];
__device__ __half g_w6r[CH * K3];
__device__ __half g_t1s[NB * K3 * PP];   // t1m [nb][k'][p]
__device__ __half g_t5s[NB * CH * PP];
__device__ __half g_t3s[NB * CH * PP];
__device__ __half g_t6s[NB * CH * PP];
__device__ __half g_t7s[NB * CH * PP];
__device__ __half g_t12s[NB * K3 * PP];  // rows k'
__device__ __half g_t9s [NB * CH * K3]; // cols k'

// ---------------------------------------------------------------------------
__device__ __forceinline__ unsigned pack2h(float v0, float v1)
{
    __half2 hh = __halves2half2(__float2half(v0), __float2half(v1));
    return *reinterpret_cast<unsigned*>(&hh);
}

__device__ __forceinline__ void mma_f16(float& d0, float& d1, float& d2, float& d3,
                                        unsigned a0, unsigned a1, unsigned a2, unsigned a3,
                                        unsigned b0, unsigned b1)
{
    asm volatile(
        "mma.sync.aligned.m16n8k16.row.col.f32.f16.f16.f32 "
        "{%0,%1,%2,%3},{%4,%5,%6,%7},{%8,%9},{%0,%1,%2,%3};\n"
        : "+f"(d0), "+f"(d1), "+f"(d2), "+f"(d3)
        : "r"(a0), "r"(a1), "r"(a2), "r"(a3), "r"(b0), "r"(b1));
}

__device__ __forceinline__ void ldsm4(unsigned& r0, unsigned& r1, unsigned& r2, unsigned& r3, unsigned a)
{
    asm volatile("ldmatrix.sync.aligned.m8n8.x4.shared.b16 {%0,%1,%2,%3},[%4];"
                 : "=r"(r0), "=r"(r1), "=r"(r2), "=r"(r3) : "r"(a));
}
__device__ __forceinline__ void ldsm4t(unsigned& r0, unsigned& r1, unsigned& r2, unsigned& r3, unsigned a)
{
    asm volatile("ldmatrix.sync.aligned.m8n8.x4.trans.shared.b16 {%0,%1,%2,%3},[%4];"
                 : "=r"(r0), "=r"(r1), "=r"(r2), "=r"(r3) : "r"(a));
}
__device__ __forceinline__ void cp16(unsigned d, const void* s)
{
    asm volatile("cp.async.ca.shared.global [%0], [%1], 16;" :: "r"(d), "l"(s));
}
__device__ __forceinline__ void cp16z(unsigned d, const void* s, int sz)
{
    asm volatile("cp.async.ca.shared.global [%0], [%1], 16, %2;" :: "r"(d), "l"(s), "r"(sz));
}

// ---------------------------------------------------------------------------
// Prep kernels
// ---------------------------------------------------------------------------
__global__ void prep_w_kernel(const float* __restrict__ w3, const float* __restrict__ w6)
{
    int idx = blockIdx.x * 256 + threadIdx.x;
    int half_n = CH * K3 / 2;
    const float* src = (idx < half_n) ? w3 : w6;
    __half* dh = (idx < half_n) ? g_w3r : g_w6r;
    int i2 = (idx % half_n) * 2;
    int o = i2 / K3;
    int kp = i2 - o * K3;
    int m = kp >> 7;
    int cp = kp & 127;
    *reinterpret_cast<unsigned*>(&dh[i2]) =
        pack2h(src[o * K3 + 3 * cp + m], src[o * K3 + 3 * (cp + 1) + m]);
}

// t1m[nb][k'=m*128+cp][p] = x[nb][cp][p + 2m-2] (zero pad in w)
__global__ void prep_t1m_kernel(const float* __restrict__ x)
{
    int i2 = (blockIdx.x * 256 + threadIdx.x) * 2;
    int p = i2 & (PP - 1);
    int r = i2 >> 12;
    int kp = r % K3;
    int nb = r / K3;
    int m = kp >> 7, cp = kp & 127;
    int w = p & 63;
    const float* xr = x + (size_t)(nb * CH + cp) * PP + (p - w);
    int sh = 2 * m - 2;
    float v0 = ((unsigned)(w + sh)     < 64u) ? xr[w + sh]     : 0.f;
    float v1 = ((unsigned)(w + 1 + sh) < 64u) ? xr[w + 1 + sh] : 0.f;
    *reinterpret_cast<unsigned*>(&g_t1s[i2]) = pack2h(v0, v1);
}

// t5 = p5 * max3_w(x)
__global__ void prep_t5_kernel(const float* __restrict__ x, const float* __restrict__ p5)
{
    int i2 = (blockIdx.x * 256 + threadIdx.x) * 2;
    if (i2 >= NB * CH * PP) return;
    int p = i2 & (PP - 1);
    int w = p & 63;
    const float* xr = x + (i2 - w);
    float v[2];
#pragma unroll
    for (int e = 0; e < 2; e++) {
        int we = w + e;
        float mx = xr[we];
        if (we >= 2) mx = fmaxf(mx, xr[we - 2]);
        if (we < 62) mx = fmaxf(mx, xr[we + 2]);
        v[e] = p5[p - w + we] * mx;
    }
    *reinterpret_cast<unsigned*>(&g_t5s[i2]) = pack2h(v[0], v[1]);
}

// t12[nb][k'=j*128+cp][p] = p12[j,h] * max(t6, max(x,t6) + max(t3, t1_j))
__global__ void prep_t12_kernel(const float* __restrict__ x, const float* __restrict__ p12)
{
    int i2 = (blockIdx.x * 256 + threadIdx.x) * 2;
    int p = i2 & (PP - 1);
    int r = i2 >> 12;
    int kp = r % K3;
    int nb = r / K3;
    int j  = kp >> 7;
    int cp = kp & 127;
    int h = p >> 6;
    int w = p & 63;
    size_t base = ((size_t)nb * CH + cp) * PP + p;
    float sc = p12[j * 64 + h];
    __half2 h6 = *reinterpret_cast<const __half2*>(&g_t6s[base]);
    __half2 h3 = *reinterpret_cast<const __half2*>(&g_t3s[base]);
    float2 f6 = __half22float2(h6);
    float2 f3 = __half22float2(h3);
    float v[2];
#pragma unroll
    for (int e = 0; e < 2; e++) {
        float xv  = x[base + e];
        float t6v = (e == 0) ? f6.x : f6.y;
        float t3v = (e == 0) ? f3.x : f3.y;
        int wq = w + e + 2 * j - 2;
        float x1 = ((unsigned)wq < 64u) ? x[base + e - (w + e) + wq] : 0.f;
        v[e] = sc * fmaxf(t6v, fmaxf(xv, t6v) + fmaxf(t3v, x1));
    }
    *reinterpret_cast<unsigned*>(&g_t12s[i2]) = pack2h(v[0], v[1]);
}

__global__ void reduce_t9s_kernel()
{
    int i2 = (blockIdx.x * 256 + threadIdx.x) * 2;
    float s0 = 0.f, s1 = 0.f;
#pragma unroll
    for (int u = 0; u < SPLITS; u++) {
        s0 += g_t9p[(size_t)u * NB * CH * K3 + i2];
        s1 += g_t9p[(size_t)u * NB * CH * K3 + i2 + 1];
    }
    *reinterpret_cast<unsigned*>(&g_t9s[i2]) =
        pack2h(s0 * (1.0f / 64.0f), s1 * (1.0f / 64.0f));
}

// ---------------------------------------------------------------------------
// mma.sync GEMM — 128 threads (4 warps as 2m x 2n), warp tile 64x64, 1 MMA.
//   MODE 0: t3  = w3r @ t1s        K=384   -> g_t3s (fp16)
//   MODE 1: t6  = w6r @ t5s(hsh)   K=384   -> g_t6s + fused t7 epilogue
//   MODE 2: t9p = t7s @ t1s^T      K=1024 slab -> g_t9p (fp32)
//   MODE 3: out = t9s @ t12s       K=384   -> out (fp32, scaled)
// ---------------------------------------------------------------------------
template <int MODE>
__global__ void __launch_bounds__(128, 2)
mma_gemm_kernel(const float* __restrict__ x, const float* __restrict__ p8,
                float* __restrict__ Cdst)
{
    extern __shared__ __half smbuf[];
    constexpr int B_EL   = (MODE == 2) ? A_ELEMS : B_ELEMS_KN;
    constexpr int STAGE  = A_ELEMS + B_EL;
    constexpr int BH_OFF = A_ELEMS;
    const int KTOT    = (MODE == 2) ? (PP / SPLITS) : K3;
    const int nb      = blockIdx.y;
    const int nt0     = blockIdx.x * 128;
    const int kbase   = (MODE == 2) ? blockIdx.z * (PP / SPLITS) : 0;

    const int tid = threadIdx.x;
    const int wid = tid >> 5, lane = tid & 31;
    const int gq = lane >> 2, cq = lane & 3;
    const int lr = lane & 15;
    const int kh8 = (lane >> 4) * 8;
    const int wm = (wid >> 1) * 64, wn = (wid & 1) * 64;
    const int h0 = nt0 >> 6;

    const unsigned sm0 = (unsigned)__cvta_generic_to_shared(smbuf);

    const __half *srcA;
    int strideA;
    if (MODE == 0)      { srcA = g_w3r; strideA = K3; }
    else if (MODE == 1) { srcA = g_w6r; strideA = K3; }
    else if (MODE == 2) { srcA = g_t7s + (size_t)nb * CH * PP + kbase; strideA = PP; }
    else                { srcA = g_t9s + (size_t)nb * CH * K3; strideA = K3; }

    const __half* srcB2 = g_t1s + ((size_t)nb * K3 + nt0) * PP + kbase;

    float acc[4][8][4];
#pragma unroll
    for (int i = 0; i < 4; i++)
#pragma unroll
        for (int j = 0; j < 8; j++)
#pragma unroll
            for (int q = 0; q < 4; q++) acc[i][j][q] = 0.f;

    auto issue_stage = [&](int kt, int buf) {
        const int sb = buf * STAGE;
        // A: 128 rows x 32 halfs
#pragma unroll
        for (int q = 0; q < 4; q++) {
            int c = tid + q * 128;
            int row = c >> 2, off = (c & 3) * 8;
            unsigned d = sm0 + 2 * (sb + row * SSTA + off);
            cp16(d, srcA + (size_t)row * strideA + kt + off);
        }
        // B
        if (MODE == 2) {
#pragma unroll
            for (int q = 0; q < 4; q++) {
                int c = tid + q * 128;
                int row = c >> 2, off = (c & 3) * 8;
                unsigned d = sm0 + 2 * (sb + BH_OFF + row * SSTA + off);
                cp16(d, srcB2 + (size_t)row * PP + kt + off);
            }
        } else if (MODE == 1) {
            int m = kt >> 7, cp0 = kt & 127;
#pragma unroll
            for (int u = 0; u < 4; u++) {
                int v = tid + u * 128;
                int r = v >> 4, ck = v & 15;
                int hc = ck >> 3, w8 = ck & 7;
                int cp = cp0 + r;
                int hp = h0 + 3 * m - 3 + hc;
                int valid = (hp >= 0 && hp < 64);
                int hpc = valid ? hp : 0;
                size_t s = (size_t)(nb * CH + cp) * PP + hpc * 64 + w8 * 8;
                unsigned d = sm0 + 2 * (sb + BH_OFF + r * SSTB + hc * 64 + w8 * 8);
                cp16z(d, g_t5s + s, valid ? 16 : 0);
            }
        } else {
            const __half* sB = (MODE == 0) ? g_t1s : g_t12s;
#pragma unroll
            for (int q = 0; q < 4; q++) {
                int c = tid + q * 128;
                int row = c >> 4, off = (c & 15) * 8;
                size_t gidx = ((size_t)nb * K3 + kt + row) * PP + nt0 + off;
                unsigned d = sm0 + 2 * (sb + BH_OFF + row * SSTB + off);
                cp16(d, sB + gidx);
            }
        }
    };

    auto compute = [&](int buf) {
        const int sb = buf * STAGE;
#pragma unroll
        for (int ks = 0; ks < 2; ks++) {
            unsigned bh[8][2];
            if (MODE == 2) {
#pragma unroll
                for (int q = 0; q < 4; q++) {
                    int nrow = wn + q * 16 + (lane & 7) + ((lane >> 4) & 1) * 8;
                    int kc = ((lane >> 3) & 1) * 8 + ks * 16;
                    unsigned a = sm0 + 2 * (sb + BH_OFF + nrow * SSTA + kc);
                    ldsm4(bh[2 * q][0], bh[2 * q][1], bh[2 * q + 1][0], bh[2 * q + 1][1], a);
                }
            } else {
#pragma unroll
                for (int q = 0; q < 4; q++) {
                    unsigned a = sm0 + 2 * (sb + BH_OFF + (ks * 16 + lr) * SSTB + wn + q * 16 + kh8);
                    ldsm4t(bh[2 * q][0], bh[2 * q][1], bh[2 * q + 1][0], bh[2 * q + 1][1], a);
                }
            }
#pragma unroll
            for (int mt = 0; mt < 4; mt++) {
                unsigned aA = sm0 + 2 * (sb + (wm + mt * 16 + lr) * SSTA + kh8 + ks * 16);
                unsigned a0, a1, a2, a3;
                ldsm4(a0, a1, a2, a3, aA);
#pragma unroll
                for (int nt = 0; nt < 8; nt++) {
                    float* a = acc[mt][nt];
                    mma_f16(a[0], a[1], a[2], a[3], a0, a1, a2, a3, bh[nt][0], bh[nt][1]);
                }
            }
        }
    };

    const int nstages = KTOT / 32;
    issue_stage(0, 0);
    asm volatile("cp.async.commit_group;");
    for (int it = 0; it < nstages; ++it) {
        const int buf = it & 1;
        if (it + 1 < nstages) {
            issue_stage((it + 1) * 32, buf ^ 1);
            asm volatile("cp.async.commit_group;");
            asm volatile("cp.async.wait_group 1;");
        } else {
            asm volatile("cp.async.wait_group 0;");
        }
        __syncthreads();
        compute(buf);
        __syncthreads();
    }

    const float scale = (MODE == 3) ? 0.051031036307982884f : 1.0f;
#pragma unroll
    for (int mt = 0; mt < 4; mt++) {
#pragma unroll
        for (int nt = 0; nt < 8; nt++) {
            int m0 = wm + mt * 16 + gq;
            int m1 = m0 + 8;
            int col = wn + nt * 8 + 2 * cq;
            float2 v0 = make_float2(acc[mt][nt][0] * scale, acc[mt][nt][1] * scale);
            float2 v1 = make_float2(acc[mt][nt][2] * scale, acc[mt][nt][3] * scale);
            if (MODE == 2) {
                float* cb = g_t9p + ((size_t)blockIdx.z * NB + nb) * CH * K3 + nt0;
                *reinterpret_cast<float2*>(&cb[(size_t)m0 * K3 + col]) = v0;
                *reinterpret_cast<float2*>(&cb[(size_t)m1 * K3 + col]) = v1;
            } else if (MODE == 3) {
                float* cb = Cdst + (size_t)nb * CH * PP + nt0;
                *reinterpret_cast<float2*>(&cb[(size_t)m0 * PP + col]) = v0;
                *reinterpret_cast<float2*>(&cb[(size_t)m1 * PP + col]) = v1;
            } else {
                size_t i0 = ((size_t)nb * CH + m0) * PP + nt0 + col;
                size_t i1 = ((size_t)nb * CH + m1) * PP + nt0 + col;
                if (MODE == 0) {
                    *reinterpret_cast<unsigned*>(&g_t3s[i0]) = pack2h(v0.x, v0.y);
                    *reinterpret_cast<unsigned*>(&g_t3s[i1]) = pack2h(v1.x, v1.y);
                } else {
                    *reinterpret_cast<unsigned*>(&g_t6s[i0]) = pack2h(v0.x, v0.y);
                    *reinterpret_cast<unsigned*>(&g_t6s[i1]) = pack2h(v1.x, v1.y);
                    float s0 = p8[m0], s1 = p8[m1];
                    *reinterpret_cast<unsigned*>(&g_t7s[i0]) =
                        pack2h(s0 * fmaxf(x[i0], v0.x), s0 * fmaxf(x[i0 + 1], v0.y));
                    *reinterpret_cast<unsigned*>(&g_t7s[i1]) =
                        pack2h(s1 * fmaxf(x[i1], v1.x), s1 * fmaxf(x[i1 + 1], v1.y));
                }
            }
        }
    }
}

// ---------------------------------------------------------------------------
extern "C" void kernel_launch(void* const* d_in, const int* in_sizes, int n_in,
                              void* d_out, int out_size)
{
    const float* x   = (const float*)d_in[0];
    const float* w3  = (const float*)d_in[1];
    const float* p5  = (const float*)d_in[2];
    const float* w6  = (const float*)d_in[3];
    const float* p8  = (const float*)d_in[4];
    const float* p12 = (const float*)d_in[5];
    float* out = (float*)d_out;

    const int SM01 = 2 * (A_ELEMS + B_ELEMS_KN) * 2;   // 37,888 B
    const int SM2  = 2 * (2 * A_ELEMS) * 2;            // 40,960 B
    cudaFuncSetAttribute(mma_gemm_kernel<0>, cudaFuncAttributeMaxDynamicSharedMemorySize, SM01);
    cudaFuncSetAttribute(mma_gemm_kernel<1>, cudaFuncAttributeMaxDynamicSharedMemorySize, SM01);
    cudaFuncSetAttribute(mma_gemm_kernel<2>, cudaFuncAttributeMaxDynamicSharedMemorySize, SM2);
    cudaFuncSetAttribute(mma_gemm_kernel<3>, cudaFuncAttributeMaxDynamicSharedMemorySize, SM01);

    prep_w_kernel<<<(CH * K3) / 256, 256>>>(w3, w6);
    prep_t1m_kernel<<<(NB * K3 * PP / 2) / 256, 256>>>(x);
    prep_t5_kernel<<<(NB * CH * PP / 2) / 256, 256>>>(x, p5);
    mma_gemm_kernel<0><<<dim3(32, NB), 128, SM01>>>(x, p8, nullptr);        // t3
    mma_gemm_kernel<1><<<dim3(32, NB), 128, SM01>>>(x, p8, nullptr);        // t6 + t7
    mma_gemm_kernel<2><<<dim3(3, NB, SPLITS), 128, SM2>>>(x, p8, nullptr);  // t9 partials
    reduce_t9s_kernel<<<(NB * CH * K3 / 2) / 256, 256>>>();
    prep_t12_kernel<<<(NB * K3 * PP / 2) / 256, 256>>>(x, p12);
    mma_gemm_kernel<3><<<dim3(32, NB), 128, SM01>>>(x, p8, out);            // out
}

// round 12
// speedup vs baseline: 5.7937x; 1.0280x over previous
#include <cuda_runtime.h>
#include <cuda_fp16.h>
#include <cstdint>

#define NB 32
#define CH 128
#define PP 4096        // H*W
#define K3 384         // 3*C  (k' = m*128 + cp m-major order everywhere)
#define SPLITS 4       // split-K for t9 (over p)

// smem geometry
#define SSTA 40        // [row][k32] stride (halfs)
#define SSTB 136       // [k32][n128] stride (halfs)
#define A_ELEMS (128 * SSTA)
#define B_ELEMS_KN (32 * SSTB)
#define NSTG 3         // cp.async pipeline depth

// fp32 scratch (split-K partials only)
__device__ float g_t9p[SPLITS * NB * CH * K3];
// fp16 single operands everywhere
__device__ __half g_w3r[CH * K3];
__device__ __half g_w6r[CH * K3];
__device__ __half g_t1s[NB * K3 * PP];   // t1m [nb][k'][p]
__device__ __half g_t5s[NB * CH * PP];
__device__ __half g_t3s[NB * CH * PP];
__device__ __half g_t6s[NB * CH * PP];
__device__ __half g_t7s[NB * CH * PP];
__device__ __half g_t12s[NB * K3 * PP];  // rows k'
__device__ __half g_t9s [NB * CH * K3]; // cols k'

// ---------------------------------------------------------------------------
__device__ __forceinline__ unsigned pack2h(float v0, float v1)
{
    __half2 hh = __halves2half2(__float2half(v0), __float2half(v1));
    return *reinterpret_cast<unsigned*>(&hh);
}

__device__ __forceinline__ void mma_f16(float& d0, float& d1, float& d2, float& d3,
                                        unsigned a0, unsigned a1, unsigned a2, unsigned a3,
                                        unsigned b0, unsigned b1)
{
    asm volatile(
        "mma.sync.aligned.m16n8k16.row.col.f32.f16.f16.f32 "
        "{%0,%1,%2,%3},{%4,%5,%6,%7},{%8,%9},{%0,%1,%2,%3};\n"
        : "+f"(d0), "+f"(d1), "+f"(d2), "+f"(d3)
        : "r"(a0), "r"(a1), "r"(a2), "r"(a3), "r"(b0), "r"(b1));
}

__device__ __forceinline__ void ldsm4(unsigned& r0, unsigned& r1, unsigned& r2, unsigned& r3, unsigned a)
{
    asm volatile("ldmatrix.sync.aligned.m8n8.x4.shared.b16 {%0,%1,%2,%3},[%4];"
                 : "=r"(r0), "=r"(r1), "=r"(r2), "=r"(r3) : "r"(a));
}
__device__ __forceinline__ void ldsm4t(unsigned& r0, unsigned& r1, unsigned& r2, unsigned& r3, unsigned a)
{
    asm volatile("ldmatrix.sync.aligned.m8n8.x4.trans.shared.b16 {%0,%1,%2,%3},[%4];"
                 : "=r"(r0), "=r"(r1), "=r"(r2), "=r"(r3) : "r"(a));
}
__device__ __forceinline__ void cp16(unsigned d, const void* s)
{
    asm volatile("cp.async.ca.shared.global [%0], [%1], 16;" :: "r"(d), "l"(s));
}
__device__ __forceinline__ void cp16z(unsigned d, const void* s, int sz)
{
    asm volatile("cp.async.ca.shared.global [%0], [%1], 16, %2;" :: "r"(d), "l"(s), "r"(sz));
}

// ---------------------------------------------------------------------------
// Prep kernels (unchanged numerics from R11)
// ---------------------------------------------------------------------------
__global__ void prep_w_kernel(const float* __restrict__ w3, const float* __restrict__ w6)
{
    int idx = blockIdx.x * 256 + threadIdx.x;
    int half_n = CH * K3 / 2;
    const float* src = (idx < half_n) ? w3 : w6;
    __half* dh = (idx < half_n) ? g_w3r : g_w6r;
    int i2 = (idx % half_n) * 2;
    int o = i2 / K3;
    int kp = i2 - o * K3;
    int m = kp >> 7;
    int cp = kp & 127;
    *reinterpret_cast<unsigned*>(&dh[i2]) =
        pack2h(src[o * K3 + 3 * cp + m], src[o * K3 + 3 * (cp + 1) + m]);
}

__global__ void prep_t1m_kernel(const float* __restrict__ x)
{
    int i2 = (blockIdx.x * 256 + threadIdx.x) * 2;
    int p = i2 & (PP - 1);
    int r = i2 >> 12;
    int kp = r % K3;
    int nb = r / K3;
    int m = kp >> 7, cp = kp & 127;
    int w = p & 63;
    const float* xr = x + (size_t)(nb * CH + cp) * PP + (p - w);
    int sh = 2 * m - 2;
    float v0 = ((unsigned)(w + sh)     < 64u) ? xr[w + sh]     : 0.f;
    float v1 = ((unsigned)(w + 1 + sh) < 64u) ? xr[w + 1 + sh] : 0.f;
    *reinterpret_cast<unsigned*>(&g_t1s[i2]) = pack2h(v0, v1);
}

__global__ void prep_t5_kernel(const float* __restrict__ x, const float* __restrict__ p5)
{
    int i2 = (blockIdx.x * 256 + threadIdx.x) * 2;
    if (i2 >= NB * CH * PP) return;
    int p = i2 & (PP - 1);
    int w = p & 63;
    const float* xr = x + (i2 - w);
    float v[2];
#pragma unroll
    for (int e = 0; e < 2; e++) {
        int we = w + e;
        float mx = xr[we];
        if (we >= 2) mx = fmaxf(mx, xr[we - 2]);
        if (we < 62) mx = fmaxf(mx, xr[we + 2]);
        v[e] = p5[p - w + we] * mx;
    }
    *reinterpret_cast<unsigned*>(&g_t5s[i2]) = pack2h(v[0], v[1]);
}

__global__ void prep_t12_kernel(const float* __restrict__ x, const float* __restrict__ p12)
{
    int i2 = (blockIdx.x * 256 + threadIdx.x) * 2;
    int p = i2 & (PP - 1);
    int r = i2 >> 12;
    int kp = r % K3;
    int nb = r / K3;
    int j  = kp >> 7;
    int cp = kp & 127;
    int h = p >> 6;
    int w = p & 63;
    size_t base = ((size_t)nb * CH + cp) * PP + p;
    float sc = p12[j * 64 + h];
    __half2 h6 = *reinterpret_cast<const __half2*>(&g_t6s[base]);
    __half2 h3 = *reinterpret_cast<const __half2*>(&g_t3s[base]);
    float2 f6 = __half22float2(h6);
    float2 f3 = __half22float2(h3);
    float v[2];
#pragma unroll
    for (int e = 0; e < 2; e++) {
        float xv  = x[base + e];
        float t6v = (e == 0) ? f6.x : f6.y;
        float t3v = (e == 0) ? f3.x : f3.y;
        int wq = w + e + 2 * j - 2;
        float x1 = ((unsigned)wq < 64u) ? x[base + e - (w + e) + wq] : 0.f;
        v[e] = sc * fmaxf(t6v, fmaxf(xv, t6v) + fmaxf(t3v, x1));
    }
    *reinterpret_cast<unsigned*>(&g_t12s[i2]) = pack2h(v[0], v[1]);
}

__global__ void reduce_t9s_kernel()
{
    int i2 = (blockIdx.x * 256 + threadIdx.x) * 2;
    float s0 = 0.f, s1 = 0.f;
#pragma unroll
    for (int u = 0; u < SPLITS; u++) {
        s0 += g_t9p[(size_t)u * NB * CH * K3 + i2];
        s1 += g_t9p[(size_t)u * NB * CH * K3 + i2 + 1];
    }
    *reinterpret_cast<unsigned*>(&g_t9s[i2]) =
        pack2h(s0 * (1.0f / 64.0f), s1 * (1.0f / 64.0f));
}

// ---------------------------------------------------------------------------
// mma.sync GEMM — 256 threads (8 warps as 2m x 4n, warp tile 64x32), 1 MMA,
// 3-stage cp.async pipeline.
//   MODE 0: t3  = w3r @ t1s        K=384   -> g_t3s (fp16)
//   MODE 1: t6  = w6r @ t5s(hsh)   K=384   -> g_t6s + fused t7 epilogue
//   MODE 2: t9p = t7s @ t1s^T      K=1024 slab -> g_t9p (fp32)
//   MODE 3: out = t9s @ t12s       K=384   -> out (fp32, scaled)
// ---------------------------------------------------------------------------
template <int MODE>
__global__ void __launch_bounds__(256, 2)
mma_gemm_kernel(const float* __restrict__ x, const float* __restrict__ p8,
                float* __restrict__ Cdst)
{
    extern __shared__ __half smbuf[];
    constexpr int B_EL   = (MODE == 2) ? A_ELEMS : B_ELEMS_KN;
    constexpr int STAGE  = A_ELEMS + B_EL;
    constexpr int BH_OFF = A_ELEMS;
    const int KTOT    = (MODE == 2) ? (PP / SPLITS) : K3;
    const int nb      = blockIdx.y;
    const int nt0     = blockIdx.x * 128;
    const int kbase   = (MODE == 2) ? blockIdx.z * (PP / SPLITS) : 0;

    const int tid = threadIdx.x;
    const int wid = tid >> 5, lane = tid & 31;
    const int gq = lane >> 2, cq = lane & 3;
    const int lr = lane & 15;
    const int kh8 = (lane >> 4) * 8;
    const int wm = (wid >> 2) * 64, wn = (wid & 3) * 32;
    const int h0 = nt0 >> 6;

    const unsigned sm0 = (unsigned)__cvta_generic_to_shared(smbuf);

    const __half *srcA;
    int strideA;
    if (MODE == 0)      { srcA = g_w3r; strideA = K3; }
    else if (MODE == 1) { srcA = g_w6r; strideA = K3; }
    else if (MODE == 2) { srcA = g_t7s + (size_t)nb * CH * PP + kbase; strideA = PP; }
    else                { srcA = g_t9s + (size_t)nb * CH * K3; strideA = K3; }

    const __half* srcB2 = g_t1s + ((size_t)nb * K3 + nt0) * PP + kbase;

    float acc[4][4][4];
#pragma unroll
    for (int i = 0; i < 4; i++)
#pragma unroll
        for (int j = 0; j < 4; j++)
#pragma unroll
            for (int q = 0; q < 4; q++) acc[i][j][q] = 0.f;

    auto issue_stage = [&](int kt, int buf) {
        const int sb = buf * STAGE;
        // A: 128 rows x 32 halfs, 512 16B-chunks over 256 threads
#pragma unroll
        for (int q = 0; q < 2; q++) {
            int c = tid + q * 256;
            int row = c >> 2, off = (c & 3) * 8;
            unsigned d = sm0 + 2 * (sb + row * SSTA + off);
            cp16(d, srcA + (size_t)row * strideA + kt + off);
        }
        // B
        if (MODE == 2) {
#pragma unroll
            for (int q = 0; q < 2; q++) {
                int c = tid + q * 256;
                int row = c >> 2, off = (c & 3) * 8;
                unsigned d = sm0 + 2 * (sb + BH_OFF + row * SSTA + off);
                cp16(d, srcB2 + (size_t)row * PP + kt + off);
            }
        } else if (MODE == 1) {
            int m = kt >> 7, cp0 = kt & 127;
#pragma unroll
            for (int u = 0; u < 2; u++) {
                int v = tid + u * 256;
                int r = v >> 4, ck = v & 15;
                int hc = ck >> 3, w8 = ck & 7;
                int cp = cp0 + r;
                int hp = h0 + 3 * m - 3 + hc;
                int valid = (hp >= 0 && hp < 64);
                int hpc = valid ? hp : 0;
                size_t s = (size_t)(nb * CH + cp) * PP + hpc * 64 + w8 * 8;
                unsigned d = sm0 + 2 * (sb + BH_OFF + r * SSTB + hc * 64 + w8 * 8);
                cp16z(d, g_t5s + s, valid ? 16 : 0);
            }
        } else {
            const __half* sB = (MODE == 0) ? g_t1s : g_t12s;
#pragma unroll
            for (int q = 0; q < 2; q++) {
                int c = tid + q * 256;
                int row = c >> 4, off = (c & 15) * 8;
                size_t gidx = ((size_t)nb * K3 + kt + row) * PP + nt0 + off;
                unsigned d = sm0 + 2 * (sb + BH_OFF + row * SSTB + off);
                cp16(d, sB + gidx);
            }
        }
    };

    auto compute = [&](int buf) {
        const int sb = buf * STAGE;
#pragma unroll
        for (int ks = 0; ks < 2; ks++) {
            unsigned bh[4][2];
            if (MODE == 2) {
#pragma unroll
                for (int q = 0; q < 2; q++) {
                    int nrow = wn + q * 16 + (lane & 7) + ((lane >> 4) & 1) * 8;
                    int kc = ((lane >> 3) & 1) * 8 + ks * 16;
                    unsigned a = sm0 + 2 * (sb + BH_OFF + nrow * SSTA + kc);
                    ldsm4(bh[2 * q][0], bh[2 * q][1], bh[2 * q + 1][0], bh[2 * q + 1][1], a);
                }
            } else {
#pragma unroll
                for (int q = 0; q < 2; q++) {
                    unsigned a = sm0 + 2 * (sb + BH_OFF + (ks * 16 + lr) * SSTB + wn + q * 16 + kh8);
                    ldsm4t(bh[2 * q][0], bh[2 * q][1], bh[2 * q + 1][0], bh[2 * q + 1][1], a);
                }
            }
#pragma unroll
            for (int mt = 0; mt < 4; mt++) {
                unsigned aA = sm0 + 2 * (sb + (wm + mt * 16 + lr) * SSTA + kh8 + ks * 16);
                unsigned a0, a1, a2, a3;
                ldsm4(a0, a1, a2, a3, aA);
#pragma unroll
                for (int nt = 0; nt < 4; nt++) {
                    float* a = acc[mt][nt];
                    mma_f16(a[0], a[1], a[2], a[3], a0, a1, a2, a3, bh[nt][0], bh[nt][1]);
                }
            }
        }
    };

    const int nstages = KTOT / 32;
    // prologue: fill pipeline
#pragma unroll
    for (int s = 0; s < NSTG; s++) {
        if (s < nstages) {
            issue_stage(s * 32, s);
            asm volatile("cp.async.commit_group;");
        }
    }
    int buf = 0;
    for (int it = 0; it < nstages; ++it) {
        int rem = nstages - 1 - it;            // groups that must remain pending
        if (rem >= 2)      asm volatile("cp.async.wait_group 2;");
        else if (rem == 1) asm volatile("cp.async.wait_group 1;");
        else               asm volatile("cp.async.wait_group 0;");
        __syncthreads();
        compute(buf);
        __syncthreads();
        if (it + NSTG < nstages) {
            issue_stage((it + NSTG) * 32, buf);
            asm volatile("cp.async.commit_group;");
        }
        buf = (buf + 1 == NSTG) ? 0 : buf + 1;
    }

    const float scale = (MODE == 3) ? 0.051031036307982884f : 1.0f;
#pragma unroll
    for (int mt = 0; mt < 4; mt++) {
#pragma unroll
        for (int nt = 0; nt < 4; nt++) {
            int m0 = wm + mt * 16 + gq;
            int m1 = m0 + 8;
            int col = wn + nt * 8 + 2 * cq;
            float2 v0 = make_float2(acc[mt][nt][0] * scale, acc[mt][nt][1] * scale);
            float2 v1 = make_float2(acc[mt][nt][2] * scale, acc[mt][nt][3] * scale);
            if (MODE == 2) {
                float* cb = g_t9p + ((size_t)blockIdx.z * NB + nb) * CH * K3 + nt0;
                *reinterpret_cast<float2*>(&cb[(size_t)m0 * K3 + col]) = v0;
                *reinterpret_cast<float2*>(&cb[(size_t)m1 * K3 + col]) = v1;
            } else if (MODE == 3) {
                float* cb = Cdst + (size_t)nb * CH * PP + nt0;
                *reinterpret_cast<float2*>(&cb[(size_t)m0 * PP + col]) = v0;
                *reinterpret_cast<float2*>(&cb[(size_t)m1 * PP + col]) = v1;
            } else {
                size_t i0 = ((size_t)nb * CH + m0) * PP + nt0 + col;
                size_t i1 = ((size_t)nb * CH + m1) * PP + nt0 + col;
                if (MODE == 0) {
                    *reinterpret_cast<unsigned*>(&g_t3s[i0]) = pack2h(v0.x, v0.y);
                    *reinterpret_cast<unsigned*>(&g_t3s[i1]) = pack2h(v1.x, v1.y);
                } else {
                    *reinterpret_cast<unsigned*>(&g_t6s[i0]) = pack2h(v0.x, v0.y);
                    *reinterpret_cast<unsigned*>(&g_t6s[i1]) = pack2h(v1.x, v1.y);
                    float s0 = p8[m0], s1 = p8[m1];
                    *reinterpret_cast<unsigned*>(&g_t7s[i0]) =
                        pack2h(s0 * fmaxf(x[i0], v0.x), s0 * fmaxf(x[i0 + 1], v0.y));
                    *reinterpret_cast<unsigned*>(&g_t7s[i1]) =
                        pack2h(s1 * fmaxf(x[i1], v1.x), s1 * fmaxf(x[i1 + 1], v1.y));
                }
            }
        }
    }
}

// ---------------------------------------------------------------------------
extern "C" void kernel_launch(void* const* d_in, const int* in_sizes, int n_in,
                              void* d_out, int out_size)
{
    const float* x   = (const float*)d_in[0];
    const float* w3  = (const float*)d_in[1];
    const float* p5  = (const float*)d_in[2];
    const float* w6  = (const float*)d_in[3];
    const float* p8  = (const float*)d_in[4];
    const float* p12 = (const float*)d_in[5];
    float* out = (float*)d_out;

    const int SM01 = NSTG * (A_ELEMS + B_ELEMS_KN) * 2;   // 56,832 B
    const int SM2  = NSTG * (2 * A_ELEMS) * 2;            // 61,440 B
    cudaFuncSetAttribute(mma_gemm_kernel<0>, cudaFuncAttributeMaxDynamicSharedMemorySize, SM01);
    cudaFuncSetAttribute(mma_gemm_kernel<1>, cudaFuncAttributeMaxDynamicSharedMemorySize, SM01);
    cudaFuncSetAttribute(mma_gemm_kernel<2>, cudaFuncAttributeMaxDynamicSharedMemorySize, SM2);
    cudaFuncSetAttribute(mma_gemm_kernel<3>, cudaFuncAttributeMaxDynamicSharedMemorySize, SM01);

    prep_w_kernel<<<(CH * K3) / 256, 256>>>(w3, w6);
    prep_t1m_kernel<<<(NB * K3 * PP / 2) / 256, 256>>>(x);
    prep_t5_kernel<<<(NB * CH * PP / 2) / 256, 256>>>(x, p5);
    mma_gemm_kernel<0><<<dim3(32, NB), 256, SM01>>>(x, p8, nullptr);        // t3
    mma_gemm_kernel<1><<<dim3(32, NB), 256, SM01>>>(x, p8, nullptr);        // t6 + t7
    mma_gemm_kernel<2><<<dim3(3, NB, SPLITS), 256, SM2>>>(x, p8, nullptr);  // t9 partials
    reduce_t9s_kernel<<<(NB * CH * K3 / 2) / 256, 256>>>();
    prep_t12_kernel<<<(NB * K3 * PP / 2) / 256, 256>>>(x, p12);
    mma_gemm_kernel<3><<<dim3(32, NB), 256, SM01>>>(x, p8, out);            // out
}